// round 10
// baseline (speedup 1.0000x reference)
#include <cuda_runtime.h>
#include <cstdint>

#define JAX_PARTITIONABLE 1

#define Bn   32
#define Gn   50
#define Hn   64
#define Wn   64
#define An   9
#define HWn  4096
#define KAn  36864
#define HALFN 9312
#define CAP  18624
#define ECAP 512

__constant__ int   c_ixmin[9]={6,11,23,4,8,16,3,5,11};
__constant__ int   c_ixmax[9]={57,52,40,59,55,47,60,58,52};
__constant__ int   c_iymin[9]={3,6,12,4,8,16,5,11,22};
__constant__ int   c_iymax[9]={60,57,51,59,55,47,58,52,41};
__constant__ float c_ax1[9]={-84.f,-176.f,-360.f,-56.f,-120.f,-248.f,-36.f,-80.f,-168.f};
__constant__ float c_ay1[9]={-40.f,-88.f,-184.f,-56.f,-120.f,-248.f,-80.f,-168.f,-344.f};
__constant__ float c_ax2[9]={99.f,191.f,375.f,71.f,135.f,263.f,51.f,95.f,183.f};
__constant__ float c_ay2[9]={55.f,103.f,199.f,71.f,135.f,263.f,95.f,183.f,359.f};
__constant__ float c_aw[9] ={184.f,368.f,736.f,128.f,256.f,512.f,88.f,176.f,352.f};
__constant__ float c_ah[9] ={96.f,192.f,384.f,128.f,256.f,512.f,176.f,352.f,704.f};
__constant__ float c_area[9]={17664.f,70656.f,282624.f,16384.f,65536.f,262144.f,15488.f,61952.f,247808.f};

// scratch — zero-initialized at load; every array below is either fully
// rewritten each run, or only read under conditions that guarantee it was
// written this run (g_v/g_arg read only when cls<2). k_final restores g_cnt.
__device__ unsigned       g_keys[Bn][4];
__device__ float          g_gtmax[Bn*Gn];      // fully rewritten each run
__device__ unsigned char  g_cls[Bn*KAn];       // fully rewritten each run
__device__ unsigned char  g_arg[Bn*KAn];       // valid where cls<2
__device__ unsigned       g_v[Bn*KAn];         // valid where cls<2
__device__ unsigned short g_nidx[KAn];         // rewritten each run by k_gtmax
__device__ int            g_cnt[Bn*2];         // cleared by k_final
__device__ unsigned       g_lv[Bn*2*CAP];
__device__ int            g_ln[Bn*2*CAP];
__device__ unsigned       g_thrV[Bn*2];        // rewritten each run
__device__ int            g_thrN[Bn*2];

// ---------------- Threefry-2x32 (bit-exact with jax) ----------------
__device__ __forceinline__ void tf2x32(unsigned k0, unsigned k1, unsigned x0, unsigned x1,
                                       unsigned& o0, unsigned& o1) {
    unsigned k2 = k0 ^ k1 ^ 0x1BD11BDAu;
    x0 += k0; x1 += k1;
#define TFR(r) { x0 += x1; x1 = (x1 << (r)) | (x1 >> (32 - (r))); x1 ^= x0; }
    TFR(13) TFR(15) TFR(26) TFR(6)   x0 += k1; x1 += k2 + 1u;
    TFR(17) TFR(29) TFR(16) TFR(24)  x0 += k2; x1 += k0 + 2u;
    TFR(13) TFR(15) TFR(26) TFR(6)   x0 += k0; x1 += k1 + 3u;
    TFR(17) TFR(29) TFR(16) TFR(24)  x0 += k1; x1 += k2 + 4u;
    TFR(13) TFR(15) TFR(26) TFR(6)   x0 += k2; x1 += k0 + 5u;
#undef TFR
    o0 = x0; o1 = x1;
}

__device__ __forceinline__ unsigned ubits(unsigned k0, unsigned k1, int n) {
#if JAX_PARTITIONABLE
    unsigned y0, y1;
    tf2x32(k0, k1, 0u, (unsigned)n, y0, y1);
    return y0 ^ y1;
#else
    unsigned y0, y1;
    if (n < HALFN) { tf2x32(k0, k1, (unsigned)n, (unsigned)(n + HALFN), y0, y1); return y0; }
    else           { tf2x32(k0, k1, (unsigned)(n - HALFN), (unsigned)n, y0, y1); return y1; }
#endif
}

__device__ __forceinline__ int compact_index(int iy, int ix, int a) {
    int n = 0;
#pragma unroll
    for (int j = 0; j < 9; j++) {
        int cy = min(iy, c_iymax[j] + 1) - c_iymin[j]; cy = max(cy, 0);
        int cx = c_ixmax[j] - c_ixmin[j] + 1;
        n += cy * cx;
        if (iy >= c_iymin[j] && iy <= c_iymax[j]) {
            int px = min(ix, c_ixmax[j] + 1) - c_ixmin[j]; px = max(px, 0);
            n += px;
            if (j < a && ix >= c_ixmin[j] && ix <= c_ixmax[j]) n += 1;
        }
    }
    return n;
}

__device__ __forceinline__ float iou_f(float ax1, float ay1, float ax2, float ay2, float areaa,
                                       float gx1, float gy1, float gx2, float gy2, float areag) {
    float iw = __fadd_rn(__fsub_rn(fminf(ax2, gx2), fmaxf(ax1, gx1)), 1.0f); iw = fmaxf(iw, 0.0f);
    float ih = __fadd_rn(__fsub_rn(fminf(ay2, gy2), fmaxf(ay1, gy1)), 1.0f); ih = fmaxf(ih, 0.0f);
    float inter = __fmul_rn(iw, ih);
    return __fdiv_rn(inter, __fsub_rn(__fadd_rn(areaa, areag), inter));
}

// conservative window for anchor type a vs gt box; cells outside have ov==0
__device__ __forceinline__ void win(int a, float gx1, float gy1, float gx2, float gy2,
                                    int& xlo, int& xhi, int& ylo, int& yhi) {
    xlo = max(c_ixmin[a], (int)floorf((gx1 - 1.0f - c_ax2[a]) * 0.0625f));
    xhi = min(c_ixmax[a], (int)ceilf((gx2 + 1.0f - c_ax1[a]) * 0.0625f));
    ylo = max(c_iymin[a], (int)floorf((gy1 - 1.0f - c_ay2[a]) * 0.0625f));
    yhi = min(c_iymax[a], (int)ceilf((gy2 + 1.0f - c_ay1[a]) * 0.0625f));
}

// one block per (b,g): windowed IoU scan, block-reduce to g_gtmax.
// Blocks <144 also build the nidx table; block 0 computes Threefry keys.
__global__ void __launch_bounds__(256) k_gtmax(const float* __restrict__ gt) {
    __shared__ float red[256];
    int blk = blockIdx.x;
    int t = threadIdx.x;
    if (blk < KAn / 256) {
        int i = blk * 256 + t;
        int a = i / HWn; int r = i - a * HWn; int iy = r >> 6; int ix = r & 63;
        g_nidx[i] = (unsigned short)compact_index(iy, ix, a);
    }
    if (blk == 0 && t < Bn) {
        unsigned f0, f1, q0, q1, b0, b1;
        tf2x32(0u, 42u, 0u, (unsigned)t, b0, b1);
        tf2x32(b0, b1, 0u, 0u, f0, f1);
        tf2x32(b0, b1, 0u, 1u, q0, q1);
        g_keys[t][0] = f0; g_keys[t][1] = f1; g_keys[t][2] = q0; g_keys[t][3] = q1;
    }
    int b = blk / Gn, g = blk - b * Gn;
    const float* gb = gt + (size_t)(b * Gn + g) * 4;
    float gx1 = gb[0], gy1 = gb[1], gx2 = gb[2], gy2 = gb[3];
    float gw = __fadd_rn(__fsub_rn(gx2, gx1), 1.0f);
    float gh = __fadd_rn(__fsub_rn(gy2, gy1), 1.0f);
    float areag = __fmul_rn(gw, gh);
    float best = 0.0f;
#pragma unroll
    for (int a = 0; a < 9; a++) {
        int xlo, xhi, ylo, yhi;
        win(a, gx1, gy1, gx2, gy2, xlo, xhi, ylo, yhi);
        int nx = xhi - xlo + 1, ny = yhi - ylo + 1;
        if (nx <= 0 || ny <= 0) continue;
        int tot = nx * ny;
        float ax1 = c_ax1[a], ay1 = c_ay1[a], ax2 = c_ax2[a], ay2 = c_ay2[a], areaa = c_area[a];
        for (int q0 = t; q0 < tot; q0 += 256) {
            int q = q0 / nx;
            int iy = ylo + q, ix = xlo + q0 - q * nx;
            float sx = (float)(ix << 4), sy = (float)(iy << 4);
            float ov = iou_f(ax1 + sx, ay1 + sy, ax2 + sx, ay2 + sy, areaa,
                             gx1, gy1, gx2, gy2, areag);
            best = fmaxf(best, ov);
        }
    }
    red[t] = best;
    __syncthreads();
    for (int s = 128; s > 0; s >>= 1) {
        if (t < s) red[t] = fmaxf(red[t], red[t + s]);
        __syncthreads();
    }
    if (t == 0) g_gtmax[blk] = red[0];
}

// anchor-centric: block = 256 anchors of one type (4 rows x 64 ix) in image b.
// Computes per-anchor max/arg/hit over the shortlist of gts whose window can
// touch this block, then labels + Threefry + list compaction (former k_label).
__global__ void __launch_bounds__(256) k_anchor(const float* __restrict__ gt) {
    __shared__ float4 sbox[Gn];
    __shared__ float2 sag[Gn];          // (area, gtmax)
    __shared__ unsigned swin[Gn];       // packed xlo,xhi,ylo,yhi bytes
    __shared__ unsigned char slist[Gn];
    __shared__ int sL;
    __shared__ int lcnt[2], lbase[2];
    int b = blockIdx.y;
    int bx = blockIdx.x;                // 0..143
    int a = bx >> 4;
    int j0 = bx * 256;
    int iy0 = (j0 - a * HWn) >> 6;      // rows iy0..iy0+3
    int t = threadIdx.x;
    if (t < 2) lcnt[t] = 0;
    if (t < Gn) {
        const float* gb = gt + (size_t)(b * Gn + t) * 4;
        float gx1 = gb[0], gy1 = gb[1], gx2 = gb[2], gy2 = gb[3];
        sbox[t] = make_float4(gx1, gy1, gx2, gy2);
        float gw = __fadd_rn(__fsub_rn(gx2, gx1), 1.0f);
        float gh = __fadd_rn(__fsub_rn(gy2, gy1), 1.0f);
        sag[t] = make_float2(__fmul_rn(gw, gh), g_gtmax[b * Gn + t]);
        int xlo, xhi, ylo, yhi;
        win(a, gx1, gy1, gx2, gy2, xlo, xhi, ylo, yhi);
        xlo = min(xlo, 64); ylo = min(ylo, 64);
        xhi = max(xhi, 0);  yhi = max(yhi, 0);
        swin[t] = ((unsigned)xlo << 24) | ((unsigned)xhi << 16) | ((unsigned)ylo << 8) | (unsigned)yhi;
    }
    __syncthreads();
    if (t == 0) {
        int c = 0;
        for (int g = 0; g < Gn; g++) {
            unsigned w = swin[g];
            int ylo = (int)((w >> 8) & 255u), yhi = (int)(w & 255u);
            if (ylo <= iy0 + 3 && yhi >= iy0) slist[c++] = (unsigned char)g;
        }
        sL = c;
    }
    __syncthreads();
    int j = j0 + t;
    int r = j - a * HWn; int iy = r >> 6; int ix = r & 63;
    unsigned char cls = 3;
    float best = 0.0f; int arg = 0; bool hit = false;
    if (!(ix < c_ixmin[a] || ix > c_ixmax[a] || iy < c_iymin[a] || iy > c_iymax[a])) {
        float sx = (float)(ix << 4), sy = (float)(iy << 4);
        float ax1 = c_ax1[a] + sx, ay1 = c_ay1[a] + sy;
        float ax2 = c_ax2[a] + sx, ay2 = c_ay2[a] + sy;
        float areaa = c_area[a];
        int L = sL;
        for (int e = 0; e < L; e++) {
            int g = slist[e];
            unsigned w = swin[g];
            int xlo = (int)(w >> 24), xhi = (int)((w >> 16) & 255u);
            int ylo = (int)((w >> 8) & 255u), yhi = (int)(w & 255u);
            if (ix < xlo || ix > xhi || iy < ylo || iy > yhi) continue;
            float4 bb = sbox[g];
            float2 ag = sag[g];
            float ov = iou_f(ax1, ay1, ax2, ay2, areaa, bb.x, bb.y, bb.z, bb.w, ag.x);
            if (ov > best) { best = ov; arg = g; }
            hit = hit || (ov == ag.y && ag.y > 0.0f);
        }
        cls = (hit || best >= 0.7f) ? (unsigned char)1
            : ((best < 0.3f) ? (unsigned char)0 : (unsigned char)2);
    }
    int c = 0, lp = 0, n = 0; unsigned v = 0;
    if (cls < 2) {
        c = cls ? 0 : 1;
        n = g_nidx[j];
        v = ubits(g_keys[b][c * 2], g_keys[b][c * 2 + 1], n) >> 9;
        g_v[(size_t)b * KAn + j] = v;
        g_arg[(size_t)b * KAn + j] = (unsigned char)arg;
        lp = atomicAdd(&lcnt[c], 1);
    }
    g_cls[(size_t)b * KAn + j] = cls;
    __syncthreads();
    if (t < 2) lbase[t] = lcnt[t] ? atomicAdd(&g_cnt[b * 2 + t], lcnt[t]) : 0;
    __syncthreads();
    if (cls < 2) {
        int p = (b * 2 + c) * CAP + lbase[c] + lp;
        g_lv[p] = v;
        g_ln[p] = n;
    }
}

__device__ void find_kth(unsigned* hist, int per, unsigned k, unsigned* wsum,
                         int* s_bin, unsigned* s_below, int tid) {
    int base = tid * per;
    unsigned mysum = 0;
    for (int x = 0; x < per; x++) mysum += hist[base + x];
    unsigned lane = tid & 31, wid = tid >> 5;
    unsigned inc = mysum;
#pragma unroll
    for (int off = 1; off < 32; off <<= 1) {
        unsigned nv = __shfl_up_sync(0xffffffffu, inc, off);
        if (lane >= off) inc += nv;
    }
    if (lane == 31) wsum[wid] = inc;
    __syncthreads();
    if (wid == 0) {
        unsigned w = wsum[lane];
        unsigned iw = w;
#pragma unroll
        for (int off = 1; off < 32; off <<= 1) {
            unsigned nv = __shfl_up_sync(0xffffffffu, iw, off);
            if (lane >= off) iw += nv;
        }
        wsum[lane] = iw - w;
    }
    __syncthreads();
    unsigned run = wsum[wid] + (inc - mysum);
    for (int x = 0; x < per; x++) {
        unsigned h = hist[base + x];
        if (run < k && k <= run + h) { *s_bin = base + x; *s_below = run; }
        run += h;
    }
    __syncthreads();
}

__global__ void __launch_bounds__(1024) k_select() {
    __shared__ unsigned hist[4096];
    __shared__ unsigned wsum[32];
    __shared__ int s_bin; __shared__ unsigned s_below;
    __shared__ unsigned s_ev[ECAP]; __shared__ int s_en[ECAP];
    __shared__ int s_cnt; __shared__ unsigned s_V; __shared__ int s_cut;
    int bc = blockIdx.x; int b = bc >> 1; int c = bc & 1;
    int tid = threadIdx.x;
    int nfg = g_cnt[b * 2 + 0], nbg = g_cnt[b * 2 + 1];
    int m = c ? nbg : nfg;
    unsigned k = c ? (unsigned)(256 - min(nfg, 128)) : 128u;
    if ((unsigned)m <= k) {
        if (tid == 0) { g_thrV[bc] = 0xFFFFFFFFu; g_thrN[bc] = 0x7FFFFFFF; }
        return;
    }
    const unsigned* lv = g_lv + (size_t)bc * CAP;
    const int* ln = g_ln + (size_t)bc * CAP;

    for (int x = tid; x < 4096; x += 1024) hist[x] = 0;
    __syncthreads();
    for (int i = tid; i < m; i += 1024) atomicAdd(&hist[lv[i] >> 11], 1u);
    __syncthreads();
    find_kth(hist, 4, k, wsum, &s_bin, &s_below, tid);
    int T = s_bin;
    int R = (int)(k - s_below);
    __syncthreads();

    if (tid == 0) s_cnt = 0;
    __syncthreads();
    for (int i = tid; i < m; i += 1024) {
        unsigned v = lv[i];
        if ((int)(v >> 11) == T) {
            int p = atomicAdd(&s_cnt, 1);
            if (p < ECAP) { s_ev[p] = v; s_en[p] = ln[i]; }
        }
    }
    __syncthreads();
    int E = min(s_cnt, ECAP);
    for (int e = tid; e < E; e += 1024) {
        unsigned ve = s_ev[e]; int ne = s_en[e];
        int rk = 0;
        for (int f = 0; f < E; f++) {
            unsigned vf = s_ev[f];
            rk += (vf < ve) || (vf == ve && s_en[f] < ne);
        }
        if (rk == R - 1) { s_V = ve; s_cut = ne; }
    }
    __syncthreads();
    if (tid == 0) { g_thrV[bc] = s_V; g_thrN[bc] = s_cut; }
}

__global__ void __launch_bounds__(256) k_final(const float* __restrict__ gt, float* __restrict__ out) {
    int b = blockIdx.y;
    int j = blockIdx.x * 256 + threadIdx.x;   // a-major
    int a = j / HWn; int r = j - a * HWn; int iy = r >> 6; int ix = r & 63;
    float label = -1.0f;
    float t0 = 0.f, t1 = 0.f, t2 = 0.f, t3 = 0.f;
    unsigned char cls = g_cls[(size_t)b * KAn + j];
    if (cls < 2) {
        int n = g_nidx[j];
        int c = cls ? 0 : 1;
        unsigned v = g_v[(size_t)b * KAn + j];
        unsigned V = g_thrV[b * 2 + c]; int cut = g_thrN[b * 2 + c];
        bool keep = (v < V) || (v == V && n <= cut);
        if (cls == 1) {
            if (keep) {
                label = 1.0f;
                int arg = g_arg[(size_t)b * KAn + j];
                const float* gb = gt + (size_t)(b * Gn + arg) * 4;
                float gx1 = gb[0], gy1 = gb[1], gx2 = gb[2], gy2 = gb[3];
                float gw = __fadd_rn(__fsub_rn(gx2, gx1), 1.0f);
                float gh = __fadd_rn(__fsub_rn(gy2, gy1), 1.0f);
                float gcx = __fadd_rn(gx1, __fmul_rn(0.5f, __fsub_rn(gw, 1.0f)));
                float gcy = __fadd_rn(gy1, __fmul_rn(0.5f, __fsub_rn(gh, 1.0f)));
                float sx = (float)(ix << 4), sy = (float)(iy << 4);
                float aw = c_aw[a], ah = c_ah[a];
                float acx = __fadd_rn(__fadd_rn(c_ax1[a], sx), __fmul_rn(0.5f, __fsub_rn(aw, 1.0f)));
                float acy = __fadd_rn(__fadd_rn(c_ay1[a], sy), __fmul_rn(0.5f, __fsub_rn(ah, 1.0f)));
                t0 = __fdiv_rn(__fsub_rn(gcx, acx), aw);
                t1 = __fdiv_rn(__fsub_rn(gcy, acy), ah);
                t2 = logf(__fdiv_rn(gw, aw));
                t3 = logf(__fdiv_rn(gh, ah));
            }
        } else {
            label = keep ? 0.0f : -1.0f;
        }
    }
    out[(size_t)b * An * HWn + (size_t)a * HWn + r] = label;
    float* reg = out + (size_t)Bn * An * HWn;
    size_t rb = (size_t)b * An * 4 * HWn + (size_t)(a * 4) * HWn + r;
    reg[rb] = t0;
    reg[rb + HWn] = t1;
    reg[rb + 2 * HWn] = t2;
    reg[rb + 3 * HWn] = t3;
    // restore load-time scratch state for the next (graph-replayed) run
    if (blockIdx.x == 0 && threadIdx.x < 2) g_cnt[b * 2 + threadIdx.x] = 0;
}

extern "C" void kernel_launch(void* const* d_in, const int* in_sizes, int n_in,
                              void* d_out, int out_size) {
    (void)in_sizes; (void)n_in; (void)out_size;
    const float* gt = (const float*)d_in[0];
    float* out = (float*)d_out;
    k_gtmax<<<Bn * Gn, 256>>>(gt);
    k_anchor<<<dim3(KAn / 256, Bn), 256>>>(gt);
    k_select<<<Bn * 2, 1024>>>();
    k_final<<<dim3(KAn / 256, Bn), 256>>>(gt, out);
}

// round 11
// speedup vs baseline: 1.3188x; 1.3188x over previous
#include <cuda_runtime.h>
#include <cstdint>

#define JAX_PARTITIONABLE 1

#define Bn   32
#define Gn   50
#define Hn   64
#define Wn   64
#define An   9
#define HWn  4096
#define KAn  36864
#define HALFN 9312
#define CAP  18624
#define CAPOV 7168
#define ECAP 512

__constant__ int   c_ixmin[9]={6,11,23,4,8,16,3,5,11};
__constant__ int   c_ixmax[9]={57,52,40,59,55,47,60,58,52};
__constant__ int   c_iymin[9]={3,6,12,4,8,16,5,11,22};
__constant__ int   c_iymax[9]={60,57,51,59,55,47,58,52,41};
__constant__ float c_ax1[9]={-84.f,-176.f,-360.f,-56.f,-120.f,-248.f,-36.f,-80.f,-168.f};
__constant__ float c_ay1[9]={-40.f,-88.f,-184.f,-56.f,-120.f,-248.f,-80.f,-168.f,-344.f};
__constant__ float c_ax2[9]={99.f,191.f,375.f,71.f,135.f,263.f,51.f,95.f,183.f};
__constant__ float c_ay2[9]={55.f,103.f,199.f,71.f,135.f,263.f,95.f,183.f,359.f};
__constant__ float c_aw[9] ={184.f,368.f,736.f,128.f,256.f,512.f,88.f,176.f,352.f};
__constant__ float c_ah[9] ={96.f,192.f,384.f,128.f,256.f,512.f,176.f,352.f,704.f};
__constant__ float c_area[9]={17664.f,70656.f,282624.f,16384.f,65536.f,262144.f,15488.f,61952.f,247808.f};

// scratch — zero-initialized at module load; k_final restores that state at the
// end of every run so each kernel_launch (incl. graph replays) is identical.
// g_key64 == 0 is a valid "no positive overlap" state: arg is only consumed for
// fg anchors, which always received at least one positive-ov atomicMax (key>0).
__device__ unsigned           g_keys[Bn][4];
__device__ unsigned long long g_key64[Bn*KAn];   // (ov_bits<<32)|(63-g)
__device__ unsigned char      g_hit[Bn*KAn];
__device__ unsigned char      g_cls[Bn*KAn];     // rewritten fully each run
__device__ unsigned           g_v[Bn*KAn];       // valid where cls<2
__device__ unsigned short     g_nidx[KAn];       // recomputed each run by k_gtpass
__device__ int                g_cnt[Bn*2];
__device__ unsigned           g_lv[Bn*2*CAP];
__device__ int                g_ln[Bn*2*CAP];
__device__ unsigned           g_thrV[Bn*2];      // rewritten each run
__device__ int                g_thrN[Bn*2];

// ---------------- Threefry-2x32 (bit-exact with jax) ----------------
__device__ __forceinline__ void tf2x32(unsigned k0, unsigned k1, unsigned x0, unsigned x1,
                                       unsigned& o0, unsigned& o1) {
    unsigned k2 = k0 ^ k1 ^ 0x1BD11BDAu;
    x0 += k0; x1 += k1;
#define TFR(r) { x0 += x1; x1 = (x1 << (r)) | (x1 >> (32 - (r))); x1 ^= x0; }
    TFR(13) TFR(15) TFR(26) TFR(6)   x0 += k1; x1 += k2 + 1u;
    TFR(17) TFR(29) TFR(16) TFR(24)  x0 += k2; x1 += k0 + 2u;
    TFR(13) TFR(15) TFR(26) TFR(6)   x0 += k0; x1 += k1 + 3u;
    TFR(17) TFR(29) TFR(16) TFR(24)  x0 += k1; x1 += k2 + 4u;
    TFR(13) TFR(15) TFR(26) TFR(6)   x0 += k2; x1 += k0 + 5u;
#undef TFR
    o0 = x0; o1 = x1;
}

__device__ __forceinline__ unsigned ubits(unsigned k0, unsigned k1, int n) {
#if JAX_PARTITIONABLE
    unsigned y0, y1;
    tf2x32(k0, k1, 0u, (unsigned)n, y0, y1);
    return y0 ^ y1;
#else
    unsigned y0, y1;
    if (n < HALFN) { tf2x32(k0, k1, (unsigned)n, (unsigned)(n + HALFN), y0, y1); return y0; }
    else           { tf2x32(k0, k1, (unsigned)(n - HALFN), (unsigned)n, y0, y1); return y1; }
#endif
}

__device__ __forceinline__ int compact_index(int iy, int ix, int a) {
    int n = 0;
#pragma unroll
    for (int j = 0; j < 9; j++) {
        int cy = min(iy, c_iymax[j] + 1) - c_iymin[j]; cy = max(cy, 0);
        int cx = c_ixmax[j] - c_ixmin[j] + 1;
        n += cy * cx;
        if (iy >= c_iymin[j] && iy <= c_iymax[j]) {
            int px = min(ix, c_ixmax[j] + 1) - c_ixmin[j]; px = max(px, 0);
            n += px;
            if (j < a && ix >= c_ixmin[j] && ix <= c_ixmax[j]) n += 1;
        }
    }
    return n;
}

__device__ __forceinline__ float iou_f(float ax1, float ay1, float ax2, float ay2, float areaa,
                                       float gx1, float gy1, float gx2, float gy2, float areag) {
    float iw = __fadd_rn(__fsub_rn(fminf(ax2, gx2), fmaxf(ax1, gx1)), 1.0f); iw = fmaxf(iw, 0.0f);
    float ih = __fadd_rn(__fsub_rn(fminf(ay2, gy2), fmaxf(ay1, gy1)), 1.0f); ih = fmaxf(ih, 0.0f);
    float inter = __fmul_rn(iw, ih);
    return __fdiv_rn(inter, __fsub_rn(__fadd_rn(areaa, areag), inter));
}

// conservative window bounds for anchor type a vs gt box
__device__ __forceinline__ void win(int a, float gx1, float gy1, float gx2, float gy2,
                                    int& xlo, int& xhi, int& ylo, int& yhi) {
    xlo = max(c_ixmin[a], (int)floorf((gx1 - 1.0f - c_ax2[a]) * 0.0625f));
    xhi = min(c_ixmax[a], (int)ceilf((gx2 + 1.0f - c_ax1[a]) * 0.0625f));
    ylo = max(c_iymin[a], (int)floorf((gy1 - 1.0f - c_ay2[a]) * 0.0625f));
    yhi = min(c_iymax[a], (int)ceilf((gy2 + 1.0f - c_ay1[a]) * 0.0625f));
}

// one block per (b,g): pass A computes windowed IoUs (cached in smem), does
// per-anchor 64-bit atomicMax of (ov,63-g), block-reduces this gt's max;
// pass B scans cached IoUs flagging ov==gt_max hits. Blocks <144 also build
// the nidx table; block 0 computes the per-image Threefry keys.
// Window iteration is division-free: thread t covers rows (t>>5)+8k, cols (t&31)+32m.
__global__ void __launch_bounds__(256) k_gtpass(const float* __restrict__ gt) {
    __shared__ float sov[CAPOV];
    __shared__ float red[256];
    int blk = blockIdx.x;
    int t = threadIdx.x;
    if (blk < KAn / 256) {
        int i = blk * 256 + t;
        int a = i / HWn; int r = i - a * HWn; int iy = r >> 6; int ix = r & 63;
        g_nidx[i] = (unsigned short)compact_index(iy, ix, a);
    }
    if (blk == 0 && t < Bn) {
        unsigned f0, f1, q0, q1, b0, b1;
        tf2x32(0u, 42u, 0u, (unsigned)t, b0, b1);
        tf2x32(b0, b1, 0u, 0u, f0, f1);
        tf2x32(b0, b1, 0u, 1u, q0, q1);
        g_keys[t][0] = f0; g_keys[t][1] = f1; g_keys[t][2] = q0; g_keys[t][3] = q1;
    }
    int b = blk / Gn, g = blk - b * Gn;
    const float* gb = gt + (size_t)(b * Gn + g) * 4;
    float gx1 = gb[0], gy1 = gb[1], gx2 = gb[2], gy2 = gb[3];
    float gw = __fadd_rn(__fsub_rn(gx2, gx1), 1.0f);
    float gh = __fadd_rn(__fsub_rn(gy2, gy1), 1.0f);
    float areag = __fmul_rn(gw, gh);
    float best = 0.0f;
    unsigned lowbits = (unsigned)(63 - g);
    int tx = t & 31, ty = t >> 5;

    int xlo9[9], ylo9[9], nx9[9], ny9[9], off9[9];
    int off = 0;
#pragma unroll
    for (int a = 0; a < 9; a++) {
        int xlo, xhi, ylo, yhi;
        win(a, gx1, gy1, gx2, gy2, xlo, xhi, ylo, yhi);
        int nx = xhi - xlo + 1, ny = yhi - ylo + 1;
        if (nx <= 0 || ny <= 0) { nx = 0; ny = 0; }
        xlo9[a] = xlo; ylo9[a] = ylo; nx9[a] = nx; ny9[a] = ny; off9[a] = off;
        off += nx * ny;
    }
    bool cache = (off <= CAPOV);

#pragma unroll
    for (int a = 0; a < 9; a++) {
        int nx = nx9[a], ny = ny9[a];
        if (nx == 0) continue;
        int xlo = xlo9[a], ylo = ylo9[a], base = off9[a];
        float ax1 = c_ax1[a], ay1 = c_ay1[a], ax2 = c_ax2[a], ay2 = c_ay2[a], areaa = c_area[a];
        for (int ry = ty; ry < ny; ry += 8) {
            int iy = ylo + ry;
            float sy = (float)(iy << 4);
            float vy1 = ay1 + sy, vy2 = ay2 + sy;
            int rowbase = base + ry * nx;
            for (int rx = tx; rx < nx; rx += 32) {
                int ix = xlo + rx;
                float sx = (float)(ix << 4);
                float ov = iou_f(ax1 + sx, vy1, ax2 + sx, vy2, areaa,
                                 gx1, gy1, gx2, gy2, areag);
                if (cache) sov[rowbase + rx] = ov;
                if (ov > 0.0f) {
                    best = fmaxf(best, ov);
                    unsigned long long key = ((unsigned long long)__float_as_uint(ov) << 32) | lowbits;
                    atomicMax(&g_key64[(size_t)b * KAn + a * HWn + (iy << 6) + ix], key);
                }
            }
        }
    }
    red[t] = best;
    __syncthreads();
    for (int s = 128; s > 0; s >>= 1) {
        if (t < s) red[t] = fmaxf(red[t], red[t + s]);
        __syncthreads();
    }
    float gm = red[0];
    if (gm <= 0.0f) return;
    // pass B: flag anchors achieving this gt's max overlap
#pragma unroll
    for (int a = 0; a < 9; a++) {
        int nx = nx9[a], ny = ny9[a];
        if (nx == 0) continue;
        int xlo = xlo9[a], ylo = ylo9[a], base = off9[a];
        float ax1 = c_ax1[a], ay1 = c_ay1[a], ax2 = c_ax2[a], ay2 = c_ay2[a], areaa = c_area[a];
        for (int ry = ty; ry < ny; ry += 8) {
            int iy = ylo + ry;
            float sy = (float)(iy << 4);
            float vy1 = ay1 + sy, vy2 = ay2 + sy;
            int rowbase = base + ry * nx;
            for (int rx = tx; rx < nx; rx += 32) {
                int ix = xlo + rx;
                float ov;
                if (cache) {
                    ov = sov[rowbase + rx];
                } else {
                    float sx = (float)(ix << 4);
                    ov = iou_f(ax1 + sx, vy1, ax2 + sx, vy2, areaa,
                               gx1, gy1, gx2, gy2, areag);
                }
                if (ov == gm) g_hit[(size_t)b * KAn + a * HWn + (iy << 6) + ix] = 1;
            }
        }
    }
}

__global__ void __launch_bounds__(256) k_label() {
    __shared__ int lcnt[2];
    __shared__ int lbase[2];
    int b = blockIdx.y;
    int t = threadIdx.x;
    if (t < 2) lcnt[t] = 0;
    __syncthreads();
    int j = blockIdx.x * 256 + t;       // a-major
    int a = j / HWn; int r = j - a * HWn; int iy = r >> 6; int ix = r & 63;
    unsigned char cls = 3;
    int c = 0, lp = 0, n = 0; unsigned v = 0;
    if (!(ix < c_ixmin[a] || ix > c_ixmax[a] || iy < c_iymin[a] || iy > c_iymax[a])) {
        unsigned long long key = g_key64[(size_t)b * KAn + j];
        float best = __uint_as_float((unsigned)(key >> 32));
        bool hit = g_hit[(size_t)b * KAn + j] != 0;
        cls = (hit || best >= 0.7f) ? (unsigned char)1
            : ((best < 0.3f) ? (unsigned char)0 : (unsigned char)2);
        if (cls < 2) {
            c = cls ? 0 : 1;
            n = g_nidx[j];
            v = ubits(g_keys[b][c * 2], g_keys[b][c * 2 + 1], n) >> 9;
            g_v[(size_t)b * KAn + j] = v;
            lp = atomicAdd(&lcnt[c], 1);
        }
    }
    g_cls[(size_t)b * KAn + j] = cls;
    __syncthreads();
    if (t < 2) lbase[t] = lcnt[t] ? atomicAdd(&g_cnt[b * 2 + t], lcnt[t]) : 0;
    __syncthreads();
    if (cls < 2) {
        int p = (b * 2 + c) * CAP + lbase[c] + lp;
        g_lv[p] = v;
        g_ln[p] = n;
    }
}

__device__ void find_kth(unsigned* hist, int per, unsigned k, unsigned* wsum,
                         int* s_bin, unsigned* s_below, int tid) {
    int base = tid * per;
    unsigned mysum = 0;
    for (int x = 0; x < per; x++) mysum += hist[base + x];
    unsigned lane = tid & 31, wid = tid >> 5;
    unsigned inc = mysum;
#pragma unroll
    for (int off = 1; off < 32; off <<= 1) {
        unsigned nv = __shfl_up_sync(0xffffffffu, inc, off);
        if (lane >= off) inc += nv;
    }
    if (lane == 31) wsum[wid] = inc;
    __syncthreads();
    if (wid == 0) {
        unsigned w = wsum[lane];
        unsigned iw = w;
#pragma unroll
        for (int off = 1; off < 32; off <<= 1) {
            unsigned nv = __shfl_up_sync(0xffffffffu, iw, off);
            if (lane >= off) iw += nv;
        }
        wsum[lane] = iw - w;
    }
    __syncthreads();
    unsigned run = wsum[wid] + (inc - mysum);
    for (int x = 0; x < per; x++) {
        unsigned h = hist[base + x];
        if (run < k && k <= run + h) { *s_bin = base + x; *s_below = run; }
        run += h;
    }
    __syncthreads();
}

__global__ void __launch_bounds__(1024) k_select() {
    __shared__ unsigned hist[4096];
    __shared__ unsigned wsum[32];
    __shared__ int s_bin; __shared__ unsigned s_below;
    __shared__ unsigned s_ev[ECAP]; __shared__ int s_en[ECAP];
    __shared__ int s_cnt; __shared__ unsigned s_V; __shared__ int s_cut;
    int bc = blockIdx.x; int b = bc >> 1; int c = bc & 1;
    int tid = threadIdx.x;
    int nfg = g_cnt[b * 2 + 0], nbg = g_cnt[b * 2 + 1];
    int m = c ? nbg : nfg;
    unsigned k = c ? (unsigned)(256 - min(nfg, 128)) : 128u;
    if ((unsigned)m <= k) {
        if (tid == 0) { g_thrV[bc] = 0xFFFFFFFFu; g_thrN[bc] = 0x7FFFFFFF; }
        return;
    }
    const unsigned* lv = g_lv + (size_t)bc * CAP;
    const int* ln = g_ln + (size_t)bc * CAP;

    // pass 1: 12-bit histogram
    for (int x = tid; x < 4096; x += 1024) hist[x] = 0;
    __syncthreads();
    for (int i = tid; i < m; i += 1024) atomicAdd(&hist[lv[i] >> 11], 1u);
    __syncthreads();
    find_kth(hist, 4, k, wsum, &s_bin, &s_below, tid);
    int T = s_bin;
    int R = (int)(k - s_below);   // rank within bin T (1-indexed)
    __syncthreads();

    // pass 2: collect all (v,n) in bin T, resolve the R-th smallest locally
    if (tid == 0) s_cnt = 0;
    __syncthreads();
    for (int i = tid; i < m; i += 1024) {
        unsigned v = lv[i];
        if ((int)(v >> 11) == T) {
            int p = atomicAdd(&s_cnt, 1);
            if (p < ECAP) { s_ev[p] = v; s_en[p] = ln[i]; }
        }
    }
    __syncthreads();
    int E = min(s_cnt, ECAP);
    for (int e = tid; e < E; e += 1024) {
        unsigned ve = s_ev[e]; int ne = s_en[e];
        int rk = 0;
        for (int f = 0; f < E; f++) {
            unsigned vf = s_ev[f];
            rk += (vf < ve) || (vf == ve && s_en[f] < ne);
        }
        if (rk == R - 1) { s_V = ve; s_cut = ne; }
    }
    __syncthreads();
    if (tid == 0) { g_thrV[bc] = s_V; g_thrN[bc] = s_cut; }
}

__global__ void __launch_bounds__(256) k_final(const float* __restrict__ gt, float* __restrict__ out) {
    int b = blockIdx.y;
    int j = blockIdx.x * 256 + threadIdx.x;   // a-major
    int a = j / HWn; int r = j - a * HWn; int iy = r >> 6; int ix = r & 63;
    float label = -1.0f;
    float t0 = 0.f, t1 = 0.f, t2 = 0.f, t3 = 0.f;
    unsigned char cls = g_cls[(size_t)b * KAn + j];
    if (cls < 2) {
        int n = g_nidx[j];
        int c = cls ? 0 : 1;
        unsigned v = g_v[(size_t)b * KAn + j];
        unsigned V = g_thrV[b * 2 + c]; int cut = g_thrN[b * 2 + c];
        bool keep = (v < V) || (v == V && n <= cut);
        if (cls == 1) {
            if (keep) {
                label = 1.0f;
                unsigned long long key = g_key64[(size_t)b * KAn + j];
                int arg = 63 - (int)(key & 0xFFFFFFFFu);
                const float* gb = gt + (size_t)(b * Gn + arg) * 4;
                float gx1 = gb[0], gy1 = gb[1], gx2 = gb[2], gy2 = gb[3];
                float gw = __fadd_rn(__fsub_rn(gx2, gx1), 1.0f);
                float gh = __fadd_rn(__fsub_rn(gy2, gy1), 1.0f);
                float gcx = __fadd_rn(gx1, __fmul_rn(0.5f, __fsub_rn(gw, 1.0f)));
                float gcy = __fadd_rn(gy1, __fmul_rn(0.5f, __fsub_rn(gh, 1.0f)));
                float sx = (float)(ix << 4), sy = (float)(iy << 4);
                float aw = c_aw[a], ah = c_ah[a];
                float acx = __fadd_rn(__fadd_rn(c_ax1[a], sx), __fmul_rn(0.5f, __fsub_rn(aw, 1.0f)));
                float acy = __fadd_rn(__fadd_rn(c_ay1[a], sy), __fmul_rn(0.5f, __fsub_rn(ah, 1.0f)));
                t0 = __fdiv_rn(__fsub_rn(gcx, acx), aw);
                t1 = __fdiv_rn(__fsub_rn(gcy, acy), ah);
                t2 = logf(__fdiv_rn(gw, aw));
                t3 = logf(__fdiv_rn(gh, ah));
            }
        } else {
            label = keep ? 0.0f : -1.0f;
        }
    }
    out[(size_t)b * An * HWn + (size_t)a * HWn + r] = label;
    float* reg = out + (size_t)Bn * An * HWn;
    size_t rb = (size_t)b * An * 4 * HWn + (size_t)(a * 4) * HWn + r;
    reg[rb] = t0;
    reg[rb + HWn] = t1;
    reg[rb + 2 * HWn] = t2;
    reg[rb + 3 * HWn] = t3;
    // restore load-time scratch state for the next (graph-replayed) run
    g_key64[(size_t)b * KAn + j] = 0ull;
    g_hit[(size_t)b * KAn + j] = 0;
    if (blockIdx.x == 0 && threadIdx.x < 2) g_cnt[b * 2 + threadIdx.x] = 0;
}

extern "C" void kernel_launch(void* const* d_in, const int* in_sizes, int n_in,
                              void* d_out, int out_size) {
    (void)in_sizes; (void)n_in; (void)out_size;
    const float* gt = (const float*)d_in[0];
    float* out = (float*)d_out;
    k_gtpass<<<Bn * Gn, 256>>>(gt);
    k_label<<<dim3(KAn / 256, Bn), 256>>>();
    k_select<<<Bn * 2, 1024>>>();
    k_final<<<dim3(KAn / 256, Bn), 256>>>(gt, out);
}

// round 12
// speedup vs baseline: 1.4824x; 1.1241x over previous
#include <cuda_runtime.h>
#include <cstdint>

#define JAX_PARTITIONABLE 1

#define Bn   32
#define Gn   50
#define Hn   64
#define Wn   64
#define An   9
#define HWn  4096
#define KAn  36864
#define HALFN 9312
#define CAP  18624
#define CAPOV 7168
#define ECAP 512

__constant__ int   c_ixmin[9]={6,11,23,4,8,16,3,5,11};
__constant__ int   c_ixmax[9]={57,52,40,59,55,47,60,58,52};
__constant__ int   c_iymin[9]={3,6,12,4,8,16,5,11,22};
__constant__ int   c_iymax[9]={60,57,51,59,55,47,58,52,41};
__constant__ float c_ax1[9]={-84.f,-176.f,-360.f,-56.f,-120.f,-248.f,-36.f,-80.f,-168.f};
__constant__ float c_ay1[9]={-40.f,-88.f,-184.f,-56.f,-120.f,-248.f,-80.f,-168.f,-344.f};
__constant__ float c_ax2[9]={99.f,191.f,375.f,71.f,135.f,263.f,51.f,95.f,183.f};
__constant__ float c_ay2[9]={55.f,103.f,199.f,71.f,135.f,263.f,95.f,183.f,359.f};
__constant__ float c_aw[9] ={184.f,368.f,736.f,128.f,256.f,512.f,88.f,176.f,352.f};
__constant__ float c_ah[9] ={96.f,192.f,384.f,128.f,256.f,512.f,176.f,352.f,704.f};
__constant__ float c_area[9]={17664.f,70656.f,282624.f,16384.f,65536.f,262144.f,15488.f,61952.f,247808.f};

// scratch — zero-initialized at module load; k_final restores that state at the
// end of every run so each kernel_launch (incl. graph replays) is identical.
// g_key64 == 0 is a valid "no positive overlap" state: arg is only consumed for
// fg anchors, which always received at least one positive-ov atomicMax (key>0).
__device__ unsigned           g_keys[Bn][4];
__device__ unsigned long long g_key64[Bn*KAn];   // (ov_bits<<32)|(63-g)
__device__ unsigned char      g_hit[Bn*KAn];
__device__ unsigned char      g_cls[Bn*KAn];     // rewritten fully each run
__device__ unsigned           g_v[Bn*KAn];       // valid where cls<2
__device__ unsigned short     g_nidx[KAn];       // recomputed each run by k_gtpass
__device__ int                g_cnt[Bn*2];
__device__ unsigned           g_lv[Bn*2*CAP];
__device__ int                g_ln[Bn*2*CAP];
__device__ unsigned           g_thrV[Bn*2];      // rewritten each run
__device__ int                g_thrN[Bn*2];

// ---------------- Threefry-2x32 (bit-exact with jax) ----------------
__device__ __forceinline__ void tf2x32(unsigned k0, unsigned k1, unsigned x0, unsigned x1,
                                       unsigned& o0, unsigned& o1) {
    unsigned k2 = k0 ^ k1 ^ 0x1BD11BDAu;
    x0 += k0; x1 += k1;
#define TFR(r) { x0 += x1; x1 = (x1 << (r)) | (x1 >> (32 - (r))); x1 ^= x0; }
    TFR(13) TFR(15) TFR(26) TFR(6)   x0 += k1; x1 += k2 + 1u;
    TFR(17) TFR(29) TFR(16) TFR(24)  x0 += k2; x1 += k0 + 2u;
    TFR(13) TFR(15) TFR(26) TFR(6)   x0 += k0; x1 += k1 + 3u;
    TFR(17) TFR(29) TFR(16) TFR(24)  x0 += k1; x1 += k2 + 4u;
    TFR(13) TFR(15) TFR(26) TFR(6)   x0 += k2; x1 += k0 + 5u;
#undef TFR
    o0 = x0; o1 = x1;
}

__device__ __forceinline__ unsigned ubits(unsigned k0, unsigned k1, int n) {
#if JAX_PARTITIONABLE
    unsigned y0, y1;
    tf2x32(k0, k1, 0u, (unsigned)n, y0, y1);
    return y0 ^ y1;
#else
    unsigned y0, y1;
    if (n < HALFN) { tf2x32(k0, k1, (unsigned)n, (unsigned)(n + HALFN), y0, y1); return y0; }
    else           { tf2x32(k0, k1, (unsigned)(n - HALFN), (unsigned)n, y0, y1); return y1; }
#endif
}

__device__ __forceinline__ int compact_index(int iy, int ix, int a) {
    int n = 0;
#pragma unroll
    for (int j = 0; j < 9; j++) {
        int cy = min(iy, c_iymax[j] + 1) - c_iymin[j]; cy = max(cy, 0);
        int cx = c_ixmax[j] - c_ixmin[j] + 1;
        n += cy * cx;
        if (iy >= c_iymin[j] && iy <= c_iymax[j]) {
            int px = min(ix, c_ixmax[j] + 1) - c_ixmin[j]; px = max(px, 0);
            n += px;
            if (j < a && ix >= c_ixmin[j] && ix <= c_ixmax[j]) n += 1;
        }
    }
    return n;
}

__device__ __forceinline__ float iou_f(float ax1, float ay1, float ax2, float ay2, float areaa,
                                       float gx1, float gy1, float gx2, float gy2, float areag) {
    float iw = __fadd_rn(__fsub_rn(fminf(ax2, gx2), fmaxf(ax1, gx1)), 1.0f); iw = fmaxf(iw, 0.0f);
    float ih = __fadd_rn(__fsub_rn(fminf(ay2, gy2), fmaxf(ay1, gy1)), 1.0f); ih = fmaxf(ih, 0.0f);
    float inter = __fmul_rn(iw, ih);
    return __fdiv_rn(inter, __fsub_rn(__fadd_rn(areaa, areag), inter));
}

// conservative window bounds for anchor type a vs gt box
__device__ __forceinline__ void win(int a, float gx1, float gy1, float gx2, float gy2,
                                    int& xlo, int& xhi, int& ylo, int& yhi) {
    xlo = max(c_ixmin[a], (int)floorf((gx1 - 1.0f - c_ax2[a]) * 0.0625f));
    xhi = min(c_ixmax[a], (int)ceilf((gx2 + 1.0f - c_ax1[a]) * 0.0625f));
    ylo = max(c_iymin[a], (int)floorf((gy1 - 1.0f - c_ay2[a]) * 0.0625f));
    yhi = min(c_iymax[a], (int)ceilf((gy2 + 1.0f - c_ay1[a]) * 0.0625f));
}

// exact q0/nx for q0,nx < 2^16 via magic multiply (m = ceil(2^32/nx))
__device__ __forceinline__ int fastdiv(int q0, unsigned m) {
    return (int)(unsigned)(((unsigned long long)(unsigned)q0 * m) >> 32);
}

// one block per (b,g): pass A computes windowed IoUs (cached in smem), does
// per-anchor 64-bit atomicMax of (ov,63-g), block-reduces this gt's max;
// pass B scans cached IoUs flagging ov==gt_max hits. Blocks <144 also build
// the nidx table; block 0 computes the per-image Threefry keys.
__global__ void __launch_bounds__(256) k_gtpass(const float* __restrict__ gt) {
    __shared__ float sov[CAPOV];
    __shared__ float red[256];
    int blk = blockIdx.x;
    int t = threadIdx.x;
    if (blk < KAn / 256) {
        int i = blk * 256 + t;
        int a = i / HWn; int r = i - a * HWn; int iy = r >> 6; int ix = r & 63;
        g_nidx[i] = (unsigned short)compact_index(iy, ix, a);
    }
    if (blk == 0 && t < Bn) {
        unsigned f0, f1, q0, q1, b0, b1;
        tf2x32(0u, 42u, 0u, (unsigned)t, b0, b1);
        tf2x32(b0, b1, 0u, 0u, f0, f1);
        tf2x32(b0, b1, 0u, 1u, q0, q1);
        g_keys[t][0] = f0; g_keys[t][1] = f1; g_keys[t][2] = q0; g_keys[t][3] = q1;
    }
    int b = blk / Gn, g = blk - b * Gn;
    const float* gb = gt + (size_t)(b * Gn + g) * 4;
    float gx1 = gb[0], gy1 = gb[1], gx2 = gb[2], gy2 = gb[3];
    float gw = __fadd_rn(__fsub_rn(gx2, gx1), 1.0f);
    float gh = __fadd_rn(__fsub_rn(gy2, gy1), 1.0f);
    float areag = __fmul_rn(gw, gh);
    float best = 0.0f;
    unsigned lowbits = (unsigned)(63 - g);

    int xlo9[9], ylo9[9], nx9[9], tot9[9], off9[9];
    unsigned mag9[9];
    int off = 0;
#pragma unroll
    for (int a = 0; a < 9; a++) {
        int xlo, xhi, ylo, yhi;
        win(a, gx1, gy1, gx2, gy2, xlo, xhi, ylo, yhi);
        int nx = xhi - xlo + 1, ny = yhi - ylo + 1;
        int tot = (nx > 0 && ny > 0) ? nx * ny : 0;
        xlo9[a] = xlo; ylo9[a] = ylo; nx9[a] = nx; tot9[a] = tot; off9[a] = off;
        mag9[a] = (tot > 0) ? (unsigned)((0x100000000ull + (unsigned)nx - 1) / (unsigned)nx) : 0u;
        off += tot;
    }
    bool cache = (off <= CAPOV);

#pragma unroll
    for (int a = 0; a < 9; a++) {
        int tot = tot9[a];
        if (tot == 0) continue;
        int xlo = xlo9[a], ylo = ylo9[a], nx = nx9[a], base = off9[a];
        unsigned mag = mag9[a];
        float ax1 = c_ax1[a], ay1 = c_ay1[a], ax2 = c_ax2[a], ay2 = c_ay2[a], areaa = c_area[a];
        for (int q0 = t; q0 < tot; q0 += 256) {
            int q = fastdiv(q0, mag);
            int iy = ylo + q, ix = xlo + q0 - q * nx;
            float sx = (float)(ix << 4), sy = (float)(iy << 4);
            float ov = iou_f(ax1 + sx, ay1 + sy, ax2 + sx, ay2 + sy, areaa,
                             gx1, gy1, gx2, gy2, areag);
            if (cache) sov[base + q0] = ov;
            if (ov > 0.0f) {
                best = fmaxf(best, ov);
                unsigned long long key = ((unsigned long long)__float_as_uint(ov) << 32) | lowbits;
                atomicMax(&g_key64[(size_t)b * KAn + a * HWn + (iy << 6) + ix], key);
            }
        }
    }
    red[t] = best;
    __syncthreads();
    for (int s = 128; s > 0; s >>= 1) {
        if (t < s) red[t] = fmaxf(red[t], red[t + s]);
        __syncthreads();
    }
    float gm = red[0];
    if (gm <= 0.0f) return;
    // pass B: flag anchors achieving this gt's max overlap
#pragma unroll
    for (int a = 0; a < 9; a++) {
        int tot = tot9[a];
        if (tot == 0) continue;
        int xlo = xlo9[a], ylo = ylo9[a], nx = nx9[a], base = off9[a];
        unsigned mag = mag9[a];
        float ax1 = c_ax1[a], ay1 = c_ay1[a], ax2 = c_ax2[a], ay2 = c_ay2[a], areaa = c_area[a];
        for (int q0 = t; q0 < tot; q0 += 256) {
            int q = fastdiv(q0, mag);
            int iy = ylo + q, ix = xlo + q0 - q * nx;
            float ov;
            if (cache) {
                ov = sov[base + q0];
            } else {
                float sx = (float)(ix << 4), sy = (float)(iy << 4);
                ov = iou_f(ax1 + sx, ay1 + sy, ax2 + sx, ay2 + sy, areaa,
                           gx1, gy1, gx2, gy2, areag);
            }
            if (ov == gm) g_hit[(size_t)b * KAn + a * HWn + (iy << 6) + ix] = 1;
        }
    }
}

__global__ void __launch_bounds__(256) k_label() {
    __shared__ int lcnt[2];
    __shared__ int lbase[2];
    int b = blockIdx.y;
    int t = threadIdx.x;
    if (t < 2) lcnt[t] = 0;
    __syncthreads();
    int j = blockIdx.x * 256 + t;       // a-major
    int a = j / HWn; int r = j - a * HWn; int iy = r >> 6; int ix = r & 63;
    unsigned char cls = 3;
    int c = 0, lp = 0, n = 0; unsigned v = 0;
    if (!(ix < c_ixmin[a] || ix > c_ixmax[a] || iy < c_iymin[a] || iy > c_iymax[a])) {
        unsigned long long key = g_key64[(size_t)b * KAn + j];
        float best = __uint_as_float((unsigned)(key >> 32));
        bool hit = g_hit[(size_t)b * KAn + j] != 0;
        cls = (hit || best >= 0.7f) ? (unsigned char)1
            : ((best < 0.3f) ? (unsigned char)0 : (unsigned char)2);
        if (cls < 2) {
            c = cls ? 0 : 1;
            n = g_nidx[j];
            v = ubits(g_keys[b][c * 2], g_keys[b][c * 2 + 1], n) >> 9;
            g_v[(size_t)b * KAn + j] = v;
            lp = atomicAdd(&lcnt[c], 1);
        }
    }
    g_cls[(size_t)b * KAn + j] = cls;
    __syncthreads();
    if (t < 2) lbase[t] = lcnt[t] ? atomicAdd(&g_cnt[b * 2 + t], lcnt[t]) : 0;
    __syncthreads();
    if (cls < 2) {
        int p = (b * 2 + c) * CAP + lbase[c] + lp;
        g_lv[p] = v;
        g_ln[p] = n;
    }
}

__device__ void find_kth(unsigned* hist, int per, unsigned k, unsigned* wsum,
                         int* s_bin, unsigned* s_below, int tid) {
    int base = tid * per;
    unsigned mysum = 0;
    for (int x = 0; x < per; x++) mysum += hist[base + x];
    unsigned lane = tid & 31, wid = tid >> 5;
    unsigned inc = mysum;
#pragma unroll
    for (int off = 1; off < 32; off <<= 1) {
        unsigned nv = __shfl_up_sync(0xffffffffu, inc, off);
        if (lane >= off) inc += nv;
    }
    if (lane == 31) wsum[wid] = inc;
    __syncthreads();
    if (wid == 0) {
        unsigned w = wsum[lane];
        unsigned iw = w;
#pragma unroll
        for (int off = 1; off < 32; off <<= 1) {
            unsigned nv = __shfl_up_sync(0xffffffffu, iw, off);
            if (lane >= off) iw += nv;
        }
        wsum[lane] = iw - w;
    }
    __syncthreads();
    unsigned run = wsum[wid] + (inc - mysum);
    for (int x = 0; x < per; x++) {
        unsigned h = hist[base + x];
        if (run < k && k <= run + h) { *s_bin = base + x; *s_below = run; }
        run += h;
    }
    __syncthreads();
}

__global__ void __launch_bounds__(1024) k_select() {
    __shared__ unsigned hist[4096];
    __shared__ unsigned wsum[32];
    __shared__ int s_bin; __shared__ unsigned s_below;
    __shared__ unsigned s_ev[ECAP]; __shared__ int s_en[ECAP];
    __shared__ int s_cnt; __shared__ unsigned s_V; __shared__ int s_cut;
    int bc = blockIdx.x; int b = bc >> 1; int c = bc & 1;
    int tid = threadIdx.x;
    int nfg = g_cnt[b * 2 + 0], nbg = g_cnt[b * 2 + 1];
    int m = c ? nbg : nfg;
    unsigned k = c ? (unsigned)(256 - min(nfg, 128)) : 128u;
    if ((unsigned)m <= k) {
        if (tid == 0) { g_thrV[bc] = 0xFFFFFFFFu; g_thrN[bc] = 0x7FFFFFFF; }
        return;
    }
    const unsigned* lv = g_lv + (size_t)bc * CAP;
    const int* ln = g_ln + (size_t)bc * CAP;

    // pass 1: 12-bit histogram
    for (int x = tid; x < 4096; x += 1024) hist[x] = 0;
    __syncthreads();
    for (int i = tid; i < m; i += 1024) atomicAdd(&hist[lv[i] >> 11], 1u);
    __syncthreads();
    find_kth(hist, 4, k, wsum, &s_bin, &s_below, tid);
    int T = s_bin;
    int R = (int)(k - s_below);   // rank within bin T (1-indexed)
    __syncthreads();

    // pass 2: collect all (v,n) in bin T, resolve the R-th smallest locally
    if (tid == 0) s_cnt = 0;
    __syncthreads();
    for (int i = tid; i < m; i += 1024) {
        unsigned v = lv[i];
        if ((int)(v >> 11) == T) {
            int p = atomicAdd(&s_cnt, 1);
            if (p < ECAP) { s_ev[p] = v; s_en[p] = ln[i]; }
        }
    }
    __syncthreads();
    int E = min(s_cnt, ECAP);
    for (int e = tid; e < E; e += 1024) {
        unsigned ve = s_ev[e]; int ne = s_en[e];
        int rk = 0;
        for (int f = 0; f < E; f++) {
            unsigned vf = s_ev[f];
            rk += (vf < ve) || (vf == ve && s_en[f] < ne);
        }
        if (rk == R - 1) { s_V = ve; s_cut = ne; }
    }
    __syncthreads();
    if (tid == 0) { g_thrV[bc] = s_V; g_thrN[bc] = s_cut; }
}

__global__ void __launch_bounds__(256) k_final(const float* __restrict__ gt, float* __restrict__ out) {
    int b = blockIdx.y;
    int j = blockIdx.x * 256 + threadIdx.x;   // a-major
    int a = j / HWn; int r = j - a * HWn; int iy = r >> 6; int ix = r & 63;
    float label = -1.0f;
    float t0 = 0.f, t1 = 0.f, t2 = 0.f, t3 = 0.f;
    unsigned char cls = g_cls[(size_t)b * KAn + j];
    if (cls < 2) {
        int n = g_nidx[j];
        int c = cls ? 0 : 1;
        unsigned v = g_v[(size_t)b * KAn + j];
        unsigned V = g_thrV[b * 2 + c]; int cut = g_thrN[b * 2 + c];
        bool keep = (v < V) || (v == V && n <= cut);
        if (cls == 1) {
            if (keep) {
                label = 1.0f;
                unsigned long long key = g_key64[(size_t)b * KAn + j];
                int arg = 63 - (int)(key & 0xFFFFFFFFu);
                const float* gb = gt + (size_t)(b * Gn + arg) * 4;
                float gx1 = gb[0], gy1 = gb[1], gx2 = gb[2], gy2 = gb[3];
                float gw = __fadd_rn(__fsub_rn(gx2, gx1), 1.0f);
                float gh = __fadd_rn(__fsub_rn(gy2, gy1), 1.0f);
                float gcx = __fadd_rn(gx1, __fmul_rn(0.5f, __fsub_rn(gw, 1.0f)));
                float gcy = __fadd_rn(gy1, __fmul_rn(0.5f, __fsub_rn(gh, 1.0f)));
                float sx = (float)(ix << 4), sy = (float)(iy << 4);
                float aw = c_aw[a], ah = c_ah[a];
                float acx = __fadd_rn(__fadd_rn(c_ax1[a], sx), __fmul_rn(0.5f, __fsub_rn(aw, 1.0f)));
                float acy = __fadd_rn(__fadd_rn(c_ay1[a], sy), __fmul_rn(0.5f, __fsub_rn(ah, 1.0f)));
                t0 = __fdiv_rn(__fsub_rn(gcx, acx), aw);
                t1 = __fdiv_rn(__fsub_rn(gcy, acy), ah);
                t2 = logf(__fdiv_rn(gw, aw));
                t3 = logf(__fdiv_rn(gh, ah));
            }
        } else {
            label = keep ? 0.0f : -1.0f;
        }
    }
    out[(size_t)b * An * HWn + (size_t)a * HWn + r] = label;
    float* reg = out + (size_t)Bn * An * HWn;
    size_t rb = (size_t)b * An * 4 * HWn + (size_t)(a * 4) * HWn + r;
    reg[rb] = t0;
    reg[rb + HWn] = t1;
    reg[rb + 2 * HWn] = t2;
    reg[rb + 3 * HWn] = t3;
    // restore load-time scratch state for the next (graph-replayed) run
    g_key64[(size_t)b * KAn + j] = 0ull;
    g_hit[(size_t)b * KAn + j] = 0;
    if (blockIdx.x == 0 && threadIdx.x < 2) g_cnt[b * 2 + threadIdx.x] = 0;
}

extern "C" void kernel_launch(void* const* d_in, const int* in_sizes, int n_in,
                              void* d_out, int out_size) {
    (void)in_sizes; (void)n_in; (void)out_size;
    const float* gt = (const float*)d_in[0];
    float* out = (float*)d_out;
    k_gtpass<<<Bn * Gn, 256>>>(gt);
    k_label<<<dim3(KAn / 256, Bn), 256>>>();
    k_select<<<Bn * 2, 1024>>>();
    k_final<<<dim3(KAn / 256, Bn), 256>>>(gt, out);
}

// round 14
// speedup vs baseline: 1.6637x; 1.1223x over previous
#include <cuda_runtime.h>
#include <cstdint>

#define JAX_PARTITIONABLE 1

#define Bn   32
#define Gn   50
#define Hn   64
#define Wn   64
#define An   9
#define HWn  4096
#define KAn  36864
#define HALFN 9312
#define CAP  18624
#define CAPOV 7168
#define ECAP 512

__constant__ int   c_ixmin[9]={6,11,23,4,8,16,3,5,11};
__constant__ int   c_ixmax[9]={57,52,40,59,55,47,60,58,52};
__constant__ int   c_iymin[9]={3,6,12,4,8,16,5,11,22};
__constant__ int   c_iymax[9]={60,57,51,59,55,47,58,52,41};
__constant__ float c_ax1[9]={-84.f,-176.f,-360.f,-56.f,-120.f,-248.f,-36.f,-80.f,-168.f};
__constant__ float c_ay1[9]={-40.f,-88.f,-184.f,-56.f,-120.f,-248.f,-80.f,-168.f,-344.f};
__constant__ float c_ax2[9]={99.f,191.f,375.f,71.f,135.f,263.f,51.f,95.f,183.f};
__constant__ float c_ay2[9]={55.f,103.f,199.f,71.f,135.f,263.f,95.f,183.f,359.f};
__constant__ float c_aw[9] ={184.f,368.f,736.f,128.f,256.f,512.f,88.f,176.f,352.f};
__constant__ float c_ah[9] ={96.f,192.f,384.f,128.f,256.f,512.f,176.f,352.f,704.f};
__constant__ float c_area[9]={17664.f,70656.f,282624.f,16384.f,65536.f,262144.f,15488.f,61952.f,247808.f};

// scratch — zero-initialized at module load; k_label/k_final restore that state
// every run so each kernel_launch (incl. graph replays) is identical.
// g_key64 == 0 is a valid "no positive overlap" state: arg is only consumed for
// fg anchors, which always received at least one positive-ov atomicMax (key>0).
__device__ unsigned           g_keys[Bn][4];
__device__ unsigned long long g_key64[Bn*KAn];   // (ov_bits<<32)|(63-g); cleared by k_label
__device__ unsigned char      g_hit[Bn*KAn];     // cleared by k_label
__device__ unsigned long long g_info[Bn*KAn];    // (arg<<40)|(cls<<38)|(v<<15)|n — fully rewritten
__device__ unsigned short     g_nidx[KAn];       // recomputed each run by k_gtpass
__device__ int                g_cnt[Bn*2];       // cleared by k_final
__device__ unsigned           g_lv[Bn*2*CAP];
__device__ int                g_ln[Bn*2*CAP];
__device__ unsigned           g_thrV[Bn*2];      // rewritten each run
__device__ int                g_thrN[Bn*2];

// ---------------- Threefry-2x32 (bit-exact with jax) ----------------
__device__ __forceinline__ void tf2x32(unsigned k0, unsigned k1, unsigned x0, unsigned x1,
                                       unsigned& o0, unsigned& o1) {
    unsigned k2 = k0 ^ k1 ^ 0x1BD11BDAu;
    x0 += k0; x1 += k1;
#define TFR(r) { x0 += x1; x1 = (x1 << (r)) | (x1 >> (32 - (r))); x1 ^= x0; }
    TFR(13) TFR(15) TFR(26) TFR(6)   x0 += k1; x1 += k2 + 1u;
    TFR(17) TFR(29) TFR(16) TFR(24)  x0 += k2; x1 += k0 + 2u;
    TFR(13) TFR(15) TFR(26) TFR(6)   x0 += k0; x1 += k1 + 3u;
    TFR(17) TFR(29) TFR(16) TFR(24)  x0 += k1; x1 += k2 + 4u;
    TFR(13) TFR(15) TFR(26) TFR(6)   x0 += k2; x1 += k0 + 5u;
#undef TFR
    o0 = x0; o1 = x1;
}

__device__ __forceinline__ unsigned ubits(unsigned k0, unsigned k1, int n) {
#if JAX_PARTITIONABLE
    unsigned y0, y1;
    tf2x32(k0, k1, 0u, (unsigned)n, y0, y1);
    return y0 ^ y1;
#else
    unsigned y0, y1;
    if (n < HALFN) { tf2x32(k0, k1, (unsigned)n, (unsigned)(n + HALFN), y0, y1); return y0; }
    else           { tf2x32(k0, k1, (unsigned)(n - HALFN), (unsigned)n, y0, y1); return y1; }
#endif
}

__device__ __forceinline__ int compact_index(int iy, int ix, int a) {
    int n = 0;
#pragma unroll
    for (int j = 0; j < 9; j++) {
        int cy = min(iy, c_iymax[j] + 1) - c_iymin[j]; cy = max(cy, 0);
        int cx = c_ixmax[j] - c_ixmin[j] + 1;
        n += cy * cx;
        if (iy >= c_iymin[j] && iy <= c_iymax[j]) {
            int px = min(ix, c_ixmax[j] + 1) - c_ixmin[j]; px = max(px, 0);
            n += px;
            if (j < a && ix >= c_ixmin[j] && ix <= c_ixmax[j]) n += 1;
        }
    }
    return n;
}

__device__ __forceinline__ float iou_f(float ax1, float ay1, float ax2, float ay2, float areaa,
                                       float gx1, float gy1, float gx2, float gy2, float areag) {
    float iw = __fadd_rn(__fsub_rn(fminf(ax2, gx2), fmaxf(ax1, gx1)), 1.0f); iw = fmaxf(iw, 0.0f);
    float ih = __fadd_rn(__fsub_rn(fminf(ay2, gy2), fmaxf(ay1, gy1)), 1.0f); ih = fmaxf(ih, 0.0f);
    float inter = __fmul_rn(iw, ih);
    return __fdiv_rn(inter, __fsub_rn(__fadd_rn(areaa, areag), inter));
}

// conservative window bounds for anchor type a vs gt box
__device__ __forceinline__ void win(int a, float gx1, float gy1, float gx2, float gy2,
                                    int& xlo, int& xhi, int& ylo, int& yhi) {
    xlo = max(c_ixmin[a], (int)floorf((gx1 - 1.0f - c_ax2[a]) * 0.0625f));
    xhi = min(c_ixmax[a], (int)ceilf((gx2 + 1.0f - c_ax1[a]) * 0.0625f));
    ylo = max(c_iymin[a], (int)floorf((gy1 - 1.0f - c_ay2[a]) * 0.0625f));
    yhi = min(c_iymax[a], (int)ceilf((gy2 + 1.0f - c_ay1[a]) * 0.0625f));
}

// one block per (b,g): pass A computes windowed IoUs (cached in smem), does
// per-anchor 64-bit atomicMax of (ov,63-g), block-reduces this gt's max;
// pass B scans cached IoUs flagging ov==gt_max hits. Blocks <144 also build
// the nidx table; block 0 computes the per-image Threefry keys.
__global__ void __launch_bounds__(256) k_gtpass(const float* __restrict__ gt) {
    __shared__ float sov[CAPOV];
    __shared__ float red[256];
    int blk = blockIdx.x;
    int t = threadIdx.x;
    if (blk < KAn / 256) {
        int i = blk * 256 + t;
        int a = i / HWn; int r = i - a * HWn; int iy = r >> 6; int ix = r & 63;
        g_nidx[i] = (unsigned short)compact_index(iy, ix, a);
    }
    if (blk == 0 && t < Bn) {
        unsigned f0, f1, q0, q1, b0, b1;
        tf2x32(0u, 42u, 0u, (unsigned)t, b0, b1);
        tf2x32(b0, b1, 0u, 0u, f0, f1);
        tf2x32(b0, b1, 0u, 1u, q0, q1);
        g_keys[t][0] = f0; g_keys[t][1] = f1; g_keys[t][2] = q0; g_keys[t][3] = q1;
    }
    int b = blk / Gn, g = blk - b * Gn;
    const float* gb = gt + (size_t)(b * Gn + g) * 4;
    float gx1 = gb[0], gy1 = gb[1], gx2 = gb[2], gy2 = gb[3];
    float gw = __fadd_rn(__fsub_rn(gx2, gx1), 1.0f);
    float gh = __fadd_rn(__fsub_rn(gy2, gy1), 1.0f);
    float areag = __fmul_rn(gw, gh);
    float best = 0.0f;
    unsigned lowbits = (unsigned)(63 - g);

    int xlo9[9], ylo9[9], nx9[9], tot9[9], off9[9];
    int off = 0;
#pragma unroll
    for (int a = 0; a < 9; a++) {
        int xlo, xhi, ylo, yhi;
        win(a, gx1, gy1, gx2, gy2, xlo, xhi, ylo, yhi);
        int nx = xhi - xlo + 1, ny = yhi - ylo + 1;
        int tot = (nx > 0 && ny > 0) ? nx * ny : 0;
        xlo9[a] = xlo; ylo9[a] = ylo; nx9[a] = nx; tot9[a] = tot; off9[a] = off;
        off += tot;
    }
    bool cache = (off <= CAPOV);

#pragma unroll
    for (int a = 0; a < 9; a++) {
        int tot = tot9[a];
        if (tot == 0) continue;
        int xlo = xlo9[a], ylo = ylo9[a], nx = nx9[a], base = off9[a];
        float ax1 = c_ax1[a], ay1 = c_ay1[a], ax2 = c_ax2[a], ay2 = c_ay2[a], areaa = c_area[a];
        for (int q0 = t; q0 < tot; q0 += 256) {
            int q = q0 / nx;
            int iy = ylo + q, ix = xlo + q0 - q * nx;
            float sx = (float)(ix << 4), sy = (float)(iy << 4);
            float ov = iou_f(ax1 + sx, ay1 + sy, ax2 + sx, ay2 + sy, areaa,
                             gx1, gy1, gx2, gy2, areag);
            if (cache) sov[base + q0] = ov;
            if (ov > 0.0f) {
                best = fmaxf(best, ov);
                unsigned long long key = ((unsigned long long)__float_as_uint(ov) << 32) | lowbits;
                atomicMax(&g_key64[(size_t)b * KAn + a * HWn + (iy << 6) + ix], key);
            }
        }
    }
    red[t] = best;
    __syncthreads();
    for (int s = 128; s > 0; s >>= 1) {
        if (t < s) red[t] = fmaxf(red[t], red[t + s]);
        __syncthreads();
    }
    float gm = red[0];
    if (gm <= 0.0f) return;
    // pass B: flag anchors achieving this gt's max overlap
#pragma unroll
    for (int a = 0; a < 9; a++) {
        int tot = tot9[a];
        if (tot == 0) continue;
        int xlo = xlo9[a], ylo = ylo9[a], nx = nx9[a], base = off9[a];
        float ax1 = c_ax1[a], ay1 = c_ay1[a], ax2 = c_ax2[a], ay2 = c_ay2[a], areaa = c_area[a];
        for (int q0 = t; q0 < tot; q0 += 256) {
            int q = q0 / nx;
            int iy = ylo + q, ix = xlo + q0 - q * nx;
            float ov;
            if (cache) {
                ov = sov[base + q0];
            } else {
                float sx = (float)(ix << 4), sy = (float)(iy << 4);
                ov = iou_f(ax1 + sx, ay1 + sy, ax2 + sx, ay2 + sy, areaa,
                           gx1, gy1, gx2, gy2, areag);
            }
            if (ov == gm) g_hit[(size_t)b * KAn + a * HWn + (iy << 6) + ix] = 1;
        }
    }
}

// labels each anchor, packs (arg,cls,v,n) into g_info, compacts (v,n) lists,
// and restores g_key64/g_hit to zero (their lines are already resident here).
__global__ void __launch_bounds__(256) k_label() {
    __shared__ int lcnt[2];
    __shared__ int lbase[2];
    int b = blockIdx.y;
    int t = threadIdx.x;
    if (t < 2) lcnt[t] = 0;
    __syncthreads();
    int j = blockIdx.x * 256 + t;       // a-major
    int a = j / HWn; int r = j - a * HWn; int iy = r >> 6; int ix = r & 63;
    unsigned char cls = 3;
    int c = 0, lp = 0, n = 0, arg = 0; unsigned v = 0;
    size_t idx = (size_t)b * KAn + j;
    if (!(ix < c_ixmin[a] || ix > c_ixmax[a] || iy < c_iymin[a] || iy > c_iymax[a])) {
        unsigned long long key = g_key64[idx];
        float best = __uint_as_float((unsigned)(key >> 32));
        bool hit = g_hit[idx] != 0;
        cls = (hit || best >= 0.7f) ? (unsigned char)1
            : ((best < 0.3f) ? (unsigned char)0 : (unsigned char)2);
        if (cls < 2) {
            c = cls ? 0 : 1;
            n = g_nidx[j];
            arg = 63 - (int)(key & 0xFFFFFFFFu);
            v = ubits(g_keys[b][c * 2], g_keys[b][c * 2 + 1], n) >> 9;
            lp = atomicAdd(&lcnt[c], 1);
        }
        // restore load-time zero state (lines already resident from the reads)
        g_key64[idx] = 0ull;
        g_hit[idx] = 0;
    }
    g_info[idx] = ((unsigned long long)(unsigned)arg << 40)
                | ((unsigned long long)cls << 38)
                | ((unsigned long long)v << 15)
                | (unsigned long long)(unsigned)n;
    __syncthreads();
    if (t < 2) lbase[t] = lcnt[t] ? atomicAdd(&g_cnt[b * 2 + t], lcnt[t]) : 0;
    __syncthreads();
    if (cls < 2) {
        int p = (b * 2 + c) * CAP + lbase[c] + lp;
        g_lv[p] = v;
        g_ln[p] = n;
    }
}

__device__ void find_kth(unsigned* hist, int per, unsigned k, unsigned* wsum,
                         int* s_bin, unsigned* s_below, int tid) {
    int base = tid * per;
    unsigned mysum = 0;
    for (int x = 0; x < per; x++) mysum += hist[base + x];
    unsigned lane = tid & 31, wid = tid >> 5;
    unsigned inc = mysum;
#pragma unroll
    for (int off = 1; off < 32; off <<= 1) {
        unsigned nv = __shfl_up_sync(0xffffffffu, inc, off);
        if (lane >= off) inc += nv;
    }
    if (lane == 31) wsum[wid] = inc;
    __syncthreads();
    if (wid == 0) {
        unsigned w = wsum[lane];
        unsigned iw = w;
#pragma unroll
        for (int off = 1; off < 32; off <<= 1) {
            unsigned nv = __shfl_up_sync(0xffffffffu, iw, off);
            if (lane >= off) iw += nv;
        }
        wsum[lane] = iw - w;
    }
    __syncthreads();
    unsigned run = wsum[wid] + (inc - mysum);
    for (int x = 0; x < per; x++) {
        unsigned h = hist[base + x];
        if (run < k && k <= run + h) { *s_bin = base + x; *s_below = run; }
        run += h;
    }
    __syncthreads();
}

__global__ void __launch_bounds__(1024) k_select() {
    __shared__ unsigned hist[4096];
    __shared__ unsigned wsum[32];
    __shared__ int s_bin; __shared__ unsigned s_below;
    __shared__ unsigned s_ev[ECAP]; __shared__ int s_en[ECAP];
    __shared__ int s_cnt; __shared__ unsigned s_V; __shared__ int s_cut;
    int bc = blockIdx.x; int b = bc >> 1; int c = bc & 1;
    int tid = threadIdx.x;
    int nfg = g_cnt[b * 2 + 0], nbg = g_cnt[b * 2 + 1];
    int m = c ? nbg : nfg;
    unsigned k = c ? (unsigned)(256 - min(nfg, 128)) : 128u;
    if ((unsigned)m <= k) {
        if (tid == 0) { g_thrV[bc] = 0xFFFFFFFFu; g_thrN[bc] = 0x7FFFFFFF; }
        return;
    }
    const unsigned* lv = g_lv + (size_t)bc * CAP;
    const int* ln = g_ln + (size_t)bc * CAP;

    // pass 1: 12-bit histogram
    for (int x = tid; x < 4096; x += 1024) hist[x] = 0;
    __syncthreads();
    for (int i = tid; i < m; i += 1024) atomicAdd(&hist[lv[i] >> 11], 1u);
    __syncthreads();
    find_kth(hist, 4, k, wsum, &s_bin, &s_below, tid);
    int T = s_bin;
    int R = (int)(k - s_below);   // rank within bin T (1-indexed)
    __syncthreads();

    // pass 2: collect all (v,n) in bin T, resolve the R-th smallest locally
    if (tid == 0) s_cnt = 0;
    __syncthreads();
    for (int i = tid; i < m; i += 1024) {
        unsigned v = lv[i];
        if ((int)(v >> 11) == T) {
            int p = atomicAdd(&s_cnt, 1);
            if (p < ECAP) { s_ev[p] = v; s_en[p] = ln[i]; }
        }
    }
    __syncthreads();
    int E = min(s_cnt, ECAP);
    for (int e = tid; e < E; e += 1024) {
        unsigned ve = s_ev[e]; int ne = s_en[e];
        int rk = 0;
        for (int f = 0; f < E; f++) {
            unsigned vf = s_ev[f];
            rk += (vf < ve) || (vf == ve && s_en[f] < ne);
        }
        if (rk == R - 1) { s_V = ve; s_cut = ne; }
    }
    __syncthreads();
    if (tid == 0) { g_thrV[bc] = s_V; g_thrN[bc] = s_cut; }
}

__global__ void __launch_bounds__(256) k_final(const float* __restrict__ gt, float* __restrict__ out) {
    int b = blockIdx.y;
    int j = blockIdx.x * 256 + threadIdx.x;   // a-major
    int a = j / HWn; int r = j - a * HWn; int iy = r >> 6; int ix = r & 63;
    float label = -1.0f;
    float t0 = 0.f, t1 = 0.f, t2 = 0.f, t3 = 0.f;
    unsigned long long info = g_info[(size_t)b * KAn + j];
    unsigned cls = (unsigned)(info >> 38) & 3u;
    if (cls < 2) {
        int n = (int)(info & 0x7FFFu);
        unsigned v = (unsigned)(info >> 15) & 0x7FFFFFu;
        int c = cls ? 0 : 1;
        unsigned V = g_thrV[b * 2 + c]; int cut = g_thrN[b * 2 + c];
        bool keep = (v < V) || (v == V && n <= cut);
        if (cls == 1) {
            if (keep) {
                label = 1.0f;
                int arg = (int)(info >> 40) & 63;
                const float* gb = gt + (size_t)(b * Gn + arg) * 4;
                float gx1 = gb[0], gy1 = gb[1], gx2 = gb[2], gy2 = gb[3];
                float gw = __fadd_rn(__fsub_rn(gx2, gx1), 1.0f);
                float gh = __fadd_rn(__fsub_rn(gy2, gy1), 1.0f);
                float gcx = __fadd_rn(gx1, __fmul_rn(0.5f, __fsub_rn(gw, 1.0f)));
                float gcy = __fadd_rn(gy1, __fmul_rn(0.5f, __fsub_rn(gh, 1.0f)));
                float sx = (float)(ix << 4), sy = (float)(iy << 4);
                float aw = c_aw[a], ah = c_ah[a];
                float acx = __fadd_rn(__fadd_rn(c_ax1[a], sx), __fmul_rn(0.5f, __fsub_rn(aw, 1.0f)));
                float acy = __fadd_rn(__fadd_rn(c_ay1[a], sy), __fmul_rn(0.5f, __fsub_rn(ah, 1.0f)));
                t0 = __fdiv_rn(__fsub_rn(gcx, acx), aw);
                t1 = __fdiv_rn(__fsub_rn(gcy, acy), ah);
                t2 = logf(__fdiv_rn(gw, aw));
                t3 = logf(__fdiv_rn(gh, ah));
            }
        } else {
            label = keep ? 0.0f : -1.0f;
        }
    }
    out[(size_t)b * An * HWn + (size_t)a * HWn + r] = label;
    float* reg = out + (size_t)Bn * An * HWn;
    size_t rb = (size_t)b * An * 4 * HWn + (size_t)(a * 4) * HWn + r;
    reg[rb] = t0;
    reg[rb + HWn] = t1;
    reg[rb + 2 * HWn] = t2;
    reg[rb + 3 * HWn] = t3;
    // restore load-time scratch state for the next (graph-replayed) run
    if (blockIdx.x == 0 && threadIdx.x < 2) g_cnt[b * 2 + threadIdx.x] = 0;
}

extern "C" void kernel_launch(void* const* d_in, const int* in_sizes, int n_in,
                              void* d_out, int out_size) {
    (void)in_sizes; (void)n_in; (void)out_size;
    const float* gt = (const float*)d_in[0];
    float* out = (float*)d_out;
    k_gtpass<<<Bn * Gn, 256>>>(gt);
    k_label<<<dim3(KAn / 256, Bn), 256>>>();
    k_select<<<Bn * 2, 1024>>>();
    k_final<<<dim3(KAn / 256, Bn), 256>>>(gt, out);
}

// round 15
// speedup vs baseline: 1.7409x; 1.0464x over previous
#include <cuda_runtime.h>
#include <cstdint>

#define JAX_PARTITIONABLE 1

#define Bn   32
#define Gn   50
#define Hn   64
#define Wn   64
#define An   9
#define HWn  4096
#define KAn  36864
#define HALFN 9312
#define CAP  18624
#define ECAP 512

__constant__ int   c_ixmin[9]={6,11,23,4,8,16,3,5,11};
__constant__ int   c_ixmax[9]={57,52,40,59,55,47,60,58,52};
__constant__ int   c_iymin[9]={3,6,12,4,8,16,5,11,22};
__constant__ int   c_iymax[9]={60,57,51,59,55,47,58,52,41};
__constant__ float c_ax1[9]={-84.f,-176.f,-360.f,-56.f,-120.f,-248.f,-36.f,-80.f,-168.f};
__constant__ float c_ay1[9]={-40.f,-88.f,-184.f,-56.f,-120.f,-248.f,-80.f,-168.f,-344.f};
__constant__ float c_ax2[9]={99.f,191.f,375.f,71.f,135.f,263.f,51.f,95.f,183.f};
__constant__ float c_ay2[9]={55.f,103.f,199.f,71.f,135.f,263.f,95.f,183.f,359.f};
__constant__ float c_aw[9] ={184.f,368.f,736.f,128.f,256.f,512.f,88.f,176.f,352.f};
__constant__ float c_ah[9] ={96.f,192.f,384.f,128.f,256.f,512.f,176.f,352.f,704.f};
__constant__ float c_area[9]={17664.f,70656.f,282624.f,16384.f,65536.f,262144.f,15488.f,61952.f,247808.f};

// scratch — zero-initialized at module load; k_label/k_final restore that state
// every run so each kernel_launch (incl. graph replays) is identical.
// g_key64 == 0 is a valid "no positive overlap" state: arg is only consumed for
// fg anchors, which always received at least one positive-ov atomicMax (key>0).
__device__ unsigned           g_keys[Bn][4];
__device__ unsigned long long g_key64[Bn*KAn];   // (ov_bits<<32)|(63-g); cleared by k_label
__device__ unsigned char      g_hit[Bn*KAn];     // cleared by k_label
__device__ unsigned long long g_info[Bn*KAn];    // (arg<<40)|(cls<<38)|(v<<15)|n — fully rewritten
__device__ unsigned short     g_nidx[KAn];       // recomputed each run by k_gtpass
__device__ int                g_cnt[Bn*2];       // cleared by k_final
__device__ unsigned           g_lv[Bn*2*CAP];
__device__ int                g_ln[Bn*2*CAP];
__device__ unsigned           g_thrV[Bn*2];      // rewritten each run
__device__ int                g_thrN[Bn*2];

// ---------------- Threefry-2x32 (bit-exact with jax) ----------------
__device__ __forceinline__ void tf2x32(unsigned k0, unsigned k1, unsigned x0, unsigned x1,
                                       unsigned& o0, unsigned& o1) {
    unsigned k2 = k0 ^ k1 ^ 0x1BD11BDAu;
    x0 += k0; x1 += k1;
#define TFR(r) { x0 += x1; x1 = (x1 << (r)) | (x1 >> (32 - (r))); x1 ^= x0; }
    TFR(13) TFR(15) TFR(26) TFR(6)   x0 += k1; x1 += k2 + 1u;
    TFR(17) TFR(29) TFR(16) TFR(24)  x0 += k2; x1 += k0 + 2u;
    TFR(13) TFR(15) TFR(26) TFR(6)   x0 += k0; x1 += k1 + 3u;
    TFR(17) TFR(29) TFR(16) TFR(24)  x0 += k1; x1 += k2 + 4u;
    TFR(13) TFR(15) TFR(26) TFR(6)   x0 += k2; x1 += k0 + 5u;
#undef TFR
    o0 = x0; o1 = x1;
}

__device__ __forceinline__ unsigned ubits(unsigned k0, unsigned k1, int n) {
#if JAX_PARTITIONABLE
    unsigned y0, y1;
    tf2x32(k0, k1, 0u, (unsigned)n, y0, y1);
    return y0 ^ y1;
#else
    unsigned y0, y1;
    if (n < HALFN) { tf2x32(k0, k1, (unsigned)n, (unsigned)(n + HALFN), y0, y1); return y0; }
    else           { tf2x32(k0, k1, (unsigned)(n - HALFN), (unsigned)n, y0, y1); return y1; }
#endif
}

__device__ __forceinline__ int compact_index(int iy, int ix, int a) {
    int n = 0;
#pragma unroll
    for (int j = 0; j < 9; j++) {
        int cy = min(iy, c_iymax[j] + 1) - c_iymin[j]; cy = max(cy, 0);
        int cx = c_ixmax[j] - c_ixmin[j] + 1;
        n += cy * cx;
        if (iy >= c_iymin[j] && iy <= c_iymax[j]) {
            int px = min(ix, c_ixmax[j] + 1) - c_ixmin[j]; px = max(px, 0);
            n += px;
            if (j < a && ix >= c_ixmin[j] && ix <= c_ixmax[j]) n += 1;
        }
    }
    return n;
}

__device__ __forceinline__ float iou_f(float ax1, float ay1, float ax2, float ay2, float areaa,
                                       float gx1, float gy1, float gx2, float gy2, float areag) {
    float iw = __fadd_rn(__fsub_rn(fminf(ax2, gx2), fmaxf(ax1, gx1)), 1.0f); iw = fmaxf(iw, 0.0f);
    float ih = __fadd_rn(__fsub_rn(fminf(ay2, gy2), fmaxf(ay1, gy1)), 1.0f); ih = fmaxf(ih, 0.0f);
    float inter = __fmul_rn(iw, ih);
    return __fdiv_rn(inter, __fsub_rn(__fadd_rn(areaa, areag), inter));
}

// conservative window bounds for anchor type a vs gt box
__device__ __forceinline__ void win(int a, float gx1, float gy1, float gx2, float gy2,
                                    int& xlo, int& xhi, int& ylo, int& yhi) {
    xlo = max(c_ixmin[a], (int)floorf((gx1 - 1.0f - c_ax2[a]) * 0.0625f));
    xhi = min(c_ixmax[a], (int)ceilf((gx2 + 1.0f - c_ax1[a]) * 0.0625f));
    ylo = max(c_iymin[a], (int)floorf((gy1 - 1.0f - c_ay2[a]) * 0.0625f));
    yhi = min(c_iymax[a], (int)ceilf((gy2 + 1.0f - c_ay1[a]) * 0.0625f));
}

// one block per (b,g): pass A computes windowed IoUs, does per-anchor 64-bit
// atomicMax of (ov,63-g), block-reduces this gt's max gm. Pass B: ONLY threads
// whose local best equals gm re-walk their own cells (a hit cell's owner must
// have best==gm), recomputing the identical IEEE IoU — no smem cache needed.
// Blocks <144 also build the nidx table; block 0 computes Threefry keys.
__global__ void __launch_bounds__(256) k_gtpass(const float* __restrict__ gt) {
    __shared__ float red[256];
    int blk = blockIdx.x;
    int t = threadIdx.x;
    if (blk < KAn / 256) {
        int i = blk * 256 + t;
        int a = i / HWn; int r = i - a * HWn; int iy = r >> 6; int ix = r & 63;
        g_nidx[i] = (unsigned short)compact_index(iy, ix, a);
    }
    if (blk == 0 && t < Bn) {
        unsigned f0, f1, q0, q1, b0, b1;
        tf2x32(0u, 42u, 0u, (unsigned)t, b0, b1);
        tf2x32(b0, b1, 0u, 0u, f0, f1);
        tf2x32(b0, b1, 0u, 1u, q0, q1);
        g_keys[t][0] = f0; g_keys[t][1] = f1; g_keys[t][2] = q0; g_keys[t][3] = q1;
    }
    int b = blk / Gn, g = blk - b * Gn;
    const float* gb = gt + (size_t)(b * Gn + g) * 4;
    float gx1 = gb[0], gy1 = gb[1], gx2 = gb[2], gy2 = gb[3];
    float gw = __fadd_rn(__fsub_rn(gx2, gx1), 1.0f);
    float gh = __fadd_rn(__fsub_rn(gy2, gy1), 1.0f);
    float areag = __fmul_rn(gw, gh);
    float best = 0.0f;
    unsigned lowbits = (unsigned)(63 - g);

    int xlo9[9], ylo9[9], nx9[9], tot9[9];
#pragma unroll
    for (int a = 0; a < 9; a++) {
        int xlo, xhi, ylo, yhi;
        win(a, gx1, gy1, gx2, gy2, xlo, xhi, ylo, yhi);
        int nx = xhi - xlo + 1, ny = yhi - ylo + 1;
        int tot = (nx > 0 && ny > 0) ? nx * ny : 0;
        xlo9[a] = xlo; ylo9[a] = ylo; nx9[a] = nx; tot9[a] = tot;
    }

#pragma unroll
    for (int a = 0; a < 9; a++) {
        int tot = tot9[a];
        if (tot == 0) continue;
        int xlo = xlo9[a], ylo = ylo9[a], nx = nx9[a];
        float ax1 = c_ax1[a], ay1 = c_ay1[a], ax2 = c_ax2[a], ay2 = c_ay2[a], areaa = c_area[a];
        for (int q0 = t; q0 < tot; q0 += 256) {
            int q = q0 / nx;
            int iy = ylo + q, ix = xlo + q0 - q * nx;
            float sx = (float)(ix << 4), sy = (float)(iy << 4);
            float ov = iou_f(ax1 + sx, ay1 + sy, ax2 + sx, ay2 + sy, areaa,
                             gx1, gy1, gx2, gy2, areag);
            if (ov > 0.0f) {
                best = fmaxf(best, ov);
                unsigned long long key = ((unsigned long long)__float_as_uint(ov) << 32) | lowbits;
                atomicMax(&g_key64[(size_t)b * KAn + a * HWn + (iy << 6) + ix], key);
            }
        }
    }
    red[t] = best;
    __syncthreads();
    for (int s = 128; s > 0; s >>= 1) {
        if (t < s) red[t] = fmaxf(red[t], red[t + s]);
        __syncthreads();
    }
    float gm = red[0];
    if (gm <= 0.0f || best != gm) return;
    // pass B (rare threads only): flag my cells achieving ov == gm
#pragma unroll
    for (int a = 0; a < 9; a++) {
        int tot = tot9[a];
        if (tot == 0) continue;
        int xlo = xlo9[a], ylo = ylo9[a], nx = nx9[a];
        float ax1 = c_ax1[a], ay1 = c_ay1[a], ax2 = c_ax2[a], ay2 = c_ay2[a], areaa = c_area[a];
        for (int q0 = t; q0 < tot; q0 += 256) {
            int q = q0 / nx;
            int iy = ylo + q, ix = xlo + q0 - q * nx;
            float sx = (float)(ix << 4), sy = (float)(iy << 4);
            float ov = iou_f(ax1 + sx, ay1 + sy, ax2 + sx, ay2 + sy, areaa,
                             gx1, gy1, gx2, gy2, areag);
            if (ov == gm) g_hit[(size_t)b * KAn + a * HWn + (iy << 6) + ix] = 1;
        }
    }
}

// labels each anchor, packs (arg,cls,v,n) into g_info, compacts (v,n) lists,
// and restores g_key64/g_hit to zero (their lines are already resident here).
__global__ void __launch_bounds__(256) k_label() {
    __shared__ int lcnt[2];
    __shared__ int lbase[2];
    int b = blockIdx.y;
    int t = threadIdx.x;
    if (t < 2) lcnt[t] = 0;
    __syncthreads();
    int j = blockIdx.x * 256 + t;       // a-major
    int a = j / HWn; int r = j - a * HWn; int iy = r >> 6; int ix = r & 63;
    unsigned char cls = 3;
    int c = 0, lp = 0, n = 0, arg = 0; unsigned v = 0;
    size_t idx = (size_t)b * KAn + j;
    if (!(ix < c_ixmin[a] || ix > c_ixmax[a] || iy < c_iymin[a] || iy > c_iymax[a])) {
        unsigned long long key = g_key64[idx];
        float best = __uint_as_float((unsigned)(key >> 32));
        bool hit = g_hit[idx] != 0;
        cls = (hit || best >= 0.7f) ? (unsigned char)1
            : ((best < 0.3f) ? (unsigned char)0 : (unsigned char)2);
        if (cls < 2) {
            c = cls ? 0 : 1;
            n = g_nidx[j];
            arg = 63 - (int)(key & 0xFFFFFFFFu);
            v = ubits(g_keys[b][c * 2], g_keys[b][c * 2 + 1], n) >> 9;
            lp = atomicAdd(&lcnt[c], 1);
        }
        // restore load-time zero state (lines already resident from the reads)
        g_key64[idx] = 0ull;
        g_hit[idx] = 0;
    }
    g_info[idx] = ((unsigned long long)(unsigned)arg << 40)
                | ((unsigned long long)cls << 38)
                | ((unsigned long long)v << 15)
                | (unsigned long long)(unsigned)n;
    __syncthreads();
    if (t < 2) lbase[t] = lcnt[t] ? atomicAdd(&g_cnt[b * 2 + t], lcnt[t]) : 0;
    __syncthreads();
    if (cls < 2) {
        int p = (b * 2 + c) * CAP + lbase[c] + lp;
        g_lv[p] = v;
        g_ln[p] = n;
    }
}

__device__ void find_kth(unsigned* hist, int per, unsigned k, unsigned* wsum,
                         int* s_bin, unsigned* s_below, int tid) {
    int base = tid * per;
    unsigned mysum = 0;
    for (int x = 0; x < per; x++) mysum += hist[base + x];
    unsigned lane = tid & 31, wid = tid >> 5;
    unsigned inc = mysum;
#pragma unroll
    for (int off = 1; off < 32; off <<= 1) {
        unsigned nv = __shfl_up_sync(0xffffffffu, inc, off);
        if (lane >= off) inc += nv;
    }
    if (lane == 31) wsum[wid] = inc;
    __syncthreads();
    if (wid == 0) {
        unsigned w = wsum[lane];
        unsigned iw = w;
#pragma unroll
        for (int off = 1; off < 32; off <<= 1) {
            unsigned nv = __shfl_up_sync(0xffffffffu, iw, off);
            if (lane >= off) iw += nv;
        }
        wsum[lane] = iw - w;
    }
    __syncthreads();
    unsigned run = wsum[wid] + (inc - mysum);
    for (int x = 0; x < per; x++) {
        unsigned h = hist[base + x];
        if (run < k && k <= run + h) { *s_bin = base + x; *s_below = run; }
        run += h;
    }
    __syncthreads();
}

__global__ void __launch_bounds__(1024) k_select() {
    __shared__ unsigned hist[4096];
    __shared__ unsigned wsum[32];
    __shared__ int s_bin; __shared__ unsigned s_below;
    __shared__ unsigned s_ev[ECAP]; __shared__ int s_en[ECAP];
    __shared__ int s_cnt; __shared__ unsigned s_V; __shared__ int s_cut;
    int bc = blockIdx.x; int b = bc >> 1; int c = bc & 1;
    int tid = threadIdx.x;
    int nfg = g_cnt[b * 2 + 0], nbg = g_cnt[b * 2 + 1];
    int m = c ? nbg : nfg;
    unsigned k = c ? (unsigned)(256 - min(nfg, 128)) : 128u;
    if ((unsigned)m <= k) {
        if (tid == 0) { g_thrV[bc] = 0xFFFFFFFFu; g_thrN[bc] = 0x7FFFFFFF; }
        return;
    }
    const unsigned* lv = g_lv + (size_t)bc * CAP;
    const int* ln = g_ln + (size_t)bc * CAP;

    // pass 1: 12-bit histogram
    for (int x = tid; x < 4096; x += 1024) hist[x] = 0;
    __syncthreads();
    for (int i = tid; i < m; i += 1024) atomicAdd(&hist[lv[i] >> 11], 1u);
    __syncthreads();
    find_kth(hist, 4, k, wsum, &s_bin, &s_below, tid);
    int T = s_bin;
    int R = (int)(k - s_below);   // rank within bin T (1-indexed)
    __syncthreads();

    // pass 2: collect all (v,n) in bin T, resolve the R-th smallest locally
    if (tid == 0) s_cnt = 0;
    __syncthreads();
    for (int i = tid; i < m; i += 1024) {
        unsigned v = lv[i];
        if ((int)(v >> 11) == T) {
            int p = atomicAdd(&s_cnt, 1);
            if (p < ECAP) { s_ev[p] = v; s_en[p] = ln[i]; }
        }
    }
    __syncthreads();
    int E = min(s_cnt, ECAP);
    for (int e = tid; e < E; e += 1024) {
        unsigned ve = s_ev[e]; int ne = s_en[e];
        int rk = 0;
        for (int f = 0; f < E; f++) {
            unsigned vf = s_ev[f];
            rk += (vf < ve) || (vf == ve && s_en[f] < ne);
        }
        if (rk == R - 1) { s_V = ve; s_cut = ne; }
    }
    __syncthreads();
    if (tid == 0) { g_thrV[bc] = s_V; g_thrN[bc] = s_cut; }
}

__global__ void __launch_bounds__(256) k_final(const float* __restrict__ gt, float* __restrict__ out) {
    int b = blockIdx.y;
    int j = blockIdx.x * 256 + threadIdx.x;   // a-major
    int a = j / HWn; int r = j - a * HWn; int iy = r >> 6; int ix = r & 63;
    float label = -1.0f;
    float t0 = 0.f, t1 = 0.f, t2 = 0.f, t3 = 0.f;
    unsigned long long info = g_info[(size_t)b * KAn + j];
    unsigned cls = (unsigned)(info >> 38) & 3u;
    if (cls < 2) {
        int n = (int)(info & 0x7FFFu);
        unsigned v = (unsigned)(info >> 15) & 0x7FFFFFu;
        int c = cls ? 0 : 1;
        unsigned V = g_thrV[b * 2 + c]; int cut = g_thrN[b * 2 + c];
        bool keep = (v < V) || (v == V && n <= cut);
        if (cls == 1) {
            if (keep) {
                label = 1.0f;
                int arg = (int)(info >> 40) & 63;
                const float* gb = gt + (size_t)(b * Gn + arg) * 4;
                float gx1 = gb[0], gy1 = gb[1], gx2 = gb[2], gy2 = gb[3];
                float gw = __fadd_rn(__fsub_rn(gx2, gx1), 1.0f);
                float gh = __fadd_rn(__fsub_rn(gy2, gy1), 1.0f);
                float gcx = __fadd_rn(gx1, __fmul_rn(0.5f, __fsub_rn(gw, 1.0f)));
                float gcy = __fadd_rn(gy1, __fmul_rn(0.5f, __fsub_rn(gh, 1.0f)));
                float sx = (float)(ix << 4), sy = (float)(iy << 4);
                float aw = c_aw[a], ah = c_ah[a];
                float acx = __fadd_rn(__fadd_rn(c_ax1[a], sx), __fmul_rn(0.5f, __fsub_rn(aw, 1.0f)));
                float acy = __fadd_rn(__fadd_rn(c_ay1[a], sy), __fmul_rn(0.5f, __fsub_rn(ah, 1.0f)));
                t0 = __fdiv_rn(__fsub_rn(gcx, acx), aw);
                t1 = __fdiv_rn(__fsub_rn(gcy, acy), ah);
                t2 = logf(__fdiv_rn(gw, aw));
                t3 = logf(__fdiv_rn(gh, ah));
            }
        } else {
            label = keep ? 0.0f : -1.0f;
        }
    }
    out[(size_t)b * An * HWn + (size_t)a * HWn + r] = label;
    float* reg = out + (size_t)Bn * An * HWn;
    size_t rb = (size_t)b * An * 4 * HWn + (size_t)(a * 4) * HWn + r;
    reg[rb] = t0;
    reg[rb + HWn] = t1;
    reg[rb + 2 * HWn] = t2;
    reg[rb + 3 * HWn] = t3;
    // restore load-time scratch state for the next (graph-replayed) run
    if (blockIdx.x == 0 && threadIdx.x < 2) g_cnt[b * 2 + threadIdx.x] = 0;
}

extern "C" void kernel_launch(void* const* d_in, const int* in_sizes, int n_in,
                              void* d_out, int out_size) {
    (void)in_sizes; (void)n_in; (void)out_size;
    const float* gt = (const float*)d_in[0];
    float* out = (float*)d_out;
    k_gtpass<<<Bn * Gn, 256>>>(gt);
    k_label<<<dim3(KAn / 256, Bn), 256>>>();
    k_select<<<Bn * 2, 1024>>>();
    k_final<<<dim3(KAn / 256, Bn), 256>>>(gt, out);
}